// round 3
// baseline (speedup 1.0000x reference)
#include <cuda_runtime.h>
#include <cuda_bf16.h>
#include <math.h>
#include <stdint.h>

// Problem constants
#define BB 4096     // batch
#define CC 1000     // classes
#define DD 128      // feature dim
#define QQ 65536    // queue length
#define PROTO_M 0.99f

// ---- output layout (flat float32 concat, reference return order) ----
static const size_t OFF_CLASSFY = 0;
static const size_t OFF_CLUSTER = (size_t)BB * CC;
static const size_t OFF_CONTF   = OFF_CLUSTER + (size_t)BB * CC;
static const size_t OFF_CONTL   = OFF_CONTF + (size_t)(2 * BB + QQ) * DD;
static const size_t OFF_PROTO   = OFF_CONTL + (size_t)(2 * BB + QQ);
static const size_t OFF_QUEUE   = OFF_PROTO + (size_t)CC * DD;
static const size_t OFF_QP      = OFF_QUEUE + (size_t)QQ * DD;
static const size_t OFF_PTR     = OFF_QP + (size_t)QQ;

// scratch (no allocations allowed -> device globals)
__device__ float g_logits[(size_t)BB * CC];
__device__ int   g_labels[BB];

// ---------------------------------------------------------------------------
// ptr decode (int32 or float32 encoding) + dynamic_update_slice clamp
// ---------------------------------------------------------------------------
__device__ __forceinline__ int load_ptr_val(const void* p)
{
    int iv = *(const int*)p;
    if (iv >= 0 && iv <= QQ) return iv;       // stored as int32
    float fv = *(const float*)p;              // stored as float32
    return (int)fv;
}
__device__ __forceinline__ int clamp_ptr(int ptr)
{
    int ptrc = ptr;
    if (ptrc < 0) ptrc = 0;
    if (ptrc > QQ - BB) ptrc = QQ - BB;
    return ptrc;
}

// ---------------------------------------------------------------------------
// Kernel 1: classfy softmax + argmax(softmax * plabel). float4 row layout:
// thread t (<250) owns cols [4t, 4t+4).
// ---------------------------------------------------------------------------
__global__ __launch_bounds__(256) void classfy_kernel(
    const float4* __restrict__ logits4, const float4* __restrict__ plabel4,
    float4* __restrict__ out4, int* __restrict__ labels)
{
    const int b = blockIdx.x;
    const int tid = threadIdx.x;
    const int RF4 = CC / 4;                 // 250
    const bool act = tid < RF4;

    float4 l = make_float4(-1e30f, -1e30f, -1e30f, -1e30f);
    if (act) l = logits4[(size_t)b * RF4 + tid];

    __shared__ float s0[8];
    __shared__ float s1[8];
    __shared__ float sv[8];
    __shared__ int   si[8];

    float mx = fmaxf(fmaxf(l.x, l.y), fmaxf(l.z, l.w));
#pragma unroll
    for (int o = 16; o; o >>= 1) mx = fmaxf(mx, __shfl_xor_sync(0xffffffffu, mx, o));
    if ((tid & 31) == 0) s0[tid >> 5] = mx;
    __syncthreads();
    if (tid < 32) {
        float v = (tid < 8) ? s0[tid] : -1e30f;
#pragma unroll
        for (int o = 4; o; o >>= 1) v = fmaxf(v, __shfl_xor_sync(0xffffffffu, v, o));
        if (tid == 0) s0[0] = v;
    }
    __syncthreads();
    mx = s0[0];

    float4 e;
    e.x = __expf(l.x - mx); e.y = __expf(l.y - mx);
    e.z = __expf(l.z - mx); e.w = __expf(l.w - mx);
    float sum = act ? (e.x + e.y + e.z + e.w) : 0.f;
#pragma unroll
    for (int o = 16; o; o >>= 1) sum += __shfl_xor_sync(0xffffffffu, sum, o);
    if ((tid & 31) == 0) s1[tid >> 5] = sum;
    __syncthreads();
    if (tid < 32) {
        float v = (tid < 8) ? s1[tid] : 0.f;
#pragma unroll
        for (int o = 4; o; o >>= 1) v += __shfl_xor_sync(0xffffffffu, v, o);
        if (tid == 0) s1[0] = v;
    }
    __syncthreads();
    const float inv = 1.0f / s1[0];

    float bv = -1.0f;
    int bi = 0x7fffffff;
    if (act) {
        float4 p = plabel4[(size_t)b * RF4 + tid];
        float4 o;
        o.x = e.x * inv; o.y = e.y * inv; o.z = e.z * inv; o.w = e.w * inv;
        out4[(size_t)b * RF4 + tid] = o;
        float v0 = o.x * p.x, v1 = o.y * p.y, v2 = o.z * p.z, v3 = o.w * p.w;
        bv = v0; bi = 4 * tid;
        if (v1 > bv) { bv = v1; bi = 4 * tid + 1; }
        if (v2 > bv) { bv = v2; bi = 4 * tid + 2; }
        if (v3 > bv) { bv = v3; bi = 4 * tid + 3; }
    }
#pragma unroll
    for (int o = 16; o; o >>= 1) {
        float ov = __shfl_xor_sync(0xffffffffu, bv, o);
        int   oi = __shfl_xor_sync(0xffffffffu, bi, o);
        if (ov > bv || (ov == bv && oi < bi)) { bv = ov; bi = oi; }
    }
    if ((tid & 31) == 0) { sv[tid >> 5] = bv; si[tid >> 5] = bi; }
    __syncthreads();
    if (tid < 32) {
        float v = (tid < 8) ? sv[tid] : -1.0f;
        int   i = (tid < 8) ? si[tid] : 0x7fffffff;
#pragma unroll
        for (int o = 4; o; o >>= 1) {
            float ov = __shfl_xor_sync(0xffffffffu, v, o);
            int   oi = __shfl_xor_sync(0xffffffffu, i, o);
            if (ov > v || (ov == v && oi < i)) { v = ov; i = oi; }
        }
        if (tid == 0) labels[b] = i;
    }
}

// ---------------------------------------------------------------------------
// Kernel 2: logits = q @ protos^T with tf32 tensor cores (BM=64,BN=64,BK=64)
// ---------------------------------------------------------------------------
__device__ __forceinline__ uint32_t f32_to_tf32(float f)
{
    uint32_t r;
    asm volatile("cvt.rna.tf32.f32 %0, %1;" : "=r"(r) : "f"(f));
    return r;
}

__device__ __forceinline__ void mma_tf32(float c[4],
    uint32_t a0, uint32_t a1, uint32_t a2, uint32_t a3,
    uint32_t b0, uint32_t b1)
{
    asm volatile(
        "mma.sync.aligned.m16n8k8.row.col.f32.tf32.tf32.f32 "
        "{%0,%1,%2,%3}, {%4,%5,%6,%7}, {%8,%9}, {%0,%1,%2,%3};"
        : "+f"(c[0]), "+f"(c[1]), "+f"(c[2]), "+f"(c[3])
        : "r"(a0), "r"(a1), "r"(a2), "r"(a3), "r"(b0), "r"(b1));
}

#define TBM 64
#define TBN 64
#define TBK 64
__global__ __launch_bounds__(256) void gemm_tf32_kernel(
    const float* __restrict__ Aq, const float* __restrict__ Bp,
    float* __restrict__ Cout)
{
    __shared__ uint32_t As[TBM][TBK + 4];
    __shared__ uint32_t Bs[TBN][TBK + 4];

    const int tid  = threadIdx.x;
    const int w    = tid >> 5;
    const int lane = tid & 31;
    const int wm   = w & 1;
    const int wn   = w >> 1;
    const int g    = lane >> 2;
    const int tig  = lane & 3;
    const int m0   = blockIdx.y * TBM;
    const int n0   = blockIdx.x * TBN;

    float c[2][2][4];
#pragma unroll
    for (int mt = 0; mt < 2; mt++)
#pragma unroll
        for (int nt = 0; nt < 2; nt++)
#pragma unroll
            for (int i = 0; i < 4; i++) c[mt][nt][i] = 0.f;

    for (int kt = 0; kt < 2; kt++) {
        const int kk = kt * TBK;
#pragma unroll
        for (int p = 0; p < 4; p++) {
            int idx = p * 256 + tid;
            int r  = idx >> 4;
            int c4 = (idx & 15) * 4;
            float4 va = *(const float4*)(Aq + (size_t)(m0 + r) * DD + kk + c4);
            As[r][c4 + 0] = f32_to_tf32(va.x);
            As[r][c4 + 1] = f32_to_tf32(va.y);
            As[r][c4 + 2] = f32_to_tf32(va.z);
            As[r][c4 + 3] = f32_to_tf32(va.w);
            int n = n0 + r;
            float4 vb = make_float4(0.f, 0.f, 0.f, 0.f);
            if (n < CC) vb = *(const float4*)(Bp + (size_t)n * DD + kk + c4);
            Bs[r][c4 + 0] = f32_to_tf32(vb.x);
            Bs[r][c4 + 1] = f32_to_tf32(vb.y);
            Bs[r][c4 + 2] = f32_to_tf32(vb.z);
            Bs[r][c4 + 3] = f32_to_tf32(vb.w);
        }
        __syncthreads();

#pragma unroll
        for (int ks = 0; ks < TBK / 8; ks++) {
            const int k0 = ks * 8;
            uint32_t a[2][4], bfr[2][2];
#pragma unroll
            for (int mt = 0; mt < 2; mt++) {
                int rb = wm * 32 + mt * 16 + g;
                a[mt][0] = As[rb][k0 + tig];
                a[mt][1] = As[rb + 8][k0 + tig];
                a[mt][2] = As[rb][k0 + tig + 4];
                a[mt][3] = As[rb + 8][k0 + tig + 4];
            }
#pragma unroll
            for (int nt = 0; nt < 2; nt++) {
                int cb = wn * 16 + nt * 8 + g;
                bfr[nt][0] = Bs[cb][k0 + tig];
                bfr[nt][1] = Bs[cb][k0 + tig + 4];
            }
#pragma unroll
            for (int mt = 0; mt < 2; mt++)
#pragma unroll
                for (int nt = 0; nt < 2; nt++)
                    mma_tf32(c[mt][nt], a[mt][0], a[mt][1], a[mt][2], a[mt][3],
                             bfr[nt][0], bfr[nt][1]);
        }
        __syncthreads();
    }

#pragma unroll
    for (int mt = 0; mt < 2; mt++) {
#pragma unroll
        for (int nt = 0; nt < 2; nt++) {
            int m = m0 + wm * 32 + mt * 16 + g;
            int n = n0 + wn * 16 + nt * 8 + 2 * tig;
            if (n < CC) {
                *(float2*)(Cout + (size_t)m * CC + n) =
                    make_float2(c[mt][nt][0], c[mt][nt][1]);
                *(float2*)(Cout + (size_t)(m + 8) * CC + n) =
                    make_float2(c[mt][nt][2], c[mt][nt][3]);
            }
        }
    }
}

// ---------------------------------------------------------------------------
// Kernel 3: cluster softmax (float4 vectorized)
// ---------------------------------------------------------------------------
__global__ __launch_bounds__(256) void cluster_softmax_kernel(
    const float4* __restrict__ logits4, float4* __restrict__ out4)
{
    const int b = blockIdx.x;
    const int tid = threadIdx.x;
    const int RF4 = CC / 4;
    const bool act = tid < RF4;

    float4 l = make_float4(-1e30f, -1e30f, -1e30f, -1e30f);
    if (act) l = logits4[(size_t)b * RF4 + tid];

    __shared__ float s0[8];
    __shared__ float s1[8];

    float mx = fmaxf(fmaxf(l.x, l.y), fmaxf(l.z, l.w));
#pragma unroll
    for (int o = 16; o; o >>= 1) mx = fmaxf(mx, __shfl_xor_sync(0xffffffffu, mx, o));
    if ((tid & 31) == 0) s0[tid >> 5] = mx;
    __syncthreads();
    if (tid < 32) {
        float v = (tid < 8) ? s0[tid] : -1e30f;
#pragma unroll
        for (int o = 4; o; o >>= 1) v = fmaxf(v, __shfl_xor_sync(0xffffffffu, v, o));
        if (tid == 0) s0[0] = v;
    }
    __syncthreads();
    mx = s0[0];

    float4 e;
    e.x = __expf(l.x - mx); e.y = __expf(l.y - mx);
    e.z = __expf(l.z - mx); e.w = __expf(l.w - mx);
    float sum = act ? (e.x + e.y + e.z + e.w) : 0.f;
#pragma unroll
    for (int o = 16; o; o >>= 1) sum += __shfl_xor_sync(0xffffffffu, sum, o);
    if ((tid & 31) == 0) s1[tid >> 5] = sum;
    __syncthreads();
    if (tid < 32) {
        float v = (tid < 8) ? s1[tid] : 0.f;
#pragma unroll
        for (int o = 4; o; o >>= 1) v += __shfl_xor_sync(0xffffffffu, v, o);
        if (tid == 0) s1[0] = v;
    }
    __syncthreads();
    const float inv = 1.0f / s1[0];
    if (act) {
        float4 o;
        o.x = e.x * inv; o.y = e.y * inv; o.z = e.z * inv; o.w = e.w * inv;
        out4[(size_t)b * RF4 + tid] = o;
    }
}

// ---------------------------------------------------------------------------
// Kernel 4: prototype scatter-EMA + l2norm. One block (128 thr) per class.
// ---------------------------------------------------------------------------
__global__ __launch_bounds__(128) void proto_kernel(
    const float* __restrict__ q, const float* __restrict__ protos,
    const int* __restrict__ labels, float* __restrict__ out)
{
    const int c = blockIdx.x;
    const int t = threadIdx.x;

    __shared__ int counts[128];
    __shared__ int offs[128];
    __shared__ int idxbuf[BB];
    __shared__ int total_s;
    __shared__ float ws[4];

    const int base = t * 32;
    int cnt = 0;
#pragma unroll 8
    for (int j = 0; j < 32; j++) if (__ldg(&labels[base + j]) == c) cnt++;
    counts[t] = cnt;
    __syncthreads();
    if (t == 0) {
        int run = 0;
        for (int u = 0; u < 128; u++) { offs[u] = run; run += counts[u]; }
        total_s = run;
    }
    __syncthreads();
    int w = offs[t];
#pragma unroll 8
    for (int j = 0; j < 32; j++) {
        int i = base + j;
        if (__ldg(&labels[i]) == c) idxbuf[w++] = i;
    }
    __syncthreads();
    const int total = total_s;

    float acc = protos[(size_t)c * DD + t];
    for (int j = 0; j < total; j++) {
        acc = PROTO_M * acc + (1.0f - PROTO_M) * q[(size_t)idxbuf[j] * DD + t];
    }
    float s = acc * acc;
#pragma unroll
    for (int o = 16; o; o >>= 1) s += __shfl_xor_sync(0xffffffffu, s, o);
    if ((t & 31) == 0) ws[t >> 5] = s;
    __syncthreads();
    float tot = ws[0] + ws[1] + ws[2] + ws[3];
    float nrm = sqrtf(tot);
    float inv = 1.0f / fmaxf(nrm, 1e-12f);
    out[(size_t)c * DD + t] = acc * inv;
}

// ---------------------------------------------------------------------------
// Kernel 5: fused bulk dup + k-row scatter. Streaming cache hints (data is
// never re-read). new_qp slots in [ptrc, ptrc+B) are owned by the labels
// epilogue (skipped here) so there is NO ordering edge to that kernel.
// ---------------------------------------------------------------------------
__global__ __launch_bounds__(256) void bulkdup_kernel(
    const float4* __restrict__ q4, const float4* __restrict__ k4,
    const float4* __restrict__ queue4, const float* __restrict__ qp,
    const void* __restrict__ ptr_in,
    float4* __restrict__ contf4, float4* __restrict__ outq4,
    float* __restrict__ outqp, float* __restrict__ contl)
{
    const int i = blockIdx.x * blockDim.x + threadIdx.x;
    const int NQ4 = QQ * DD / 4;   // 2,097,152
    const int NB4 = BB * DD / 4;   // 131,072
    const int ptrc = clamp_ptr(load_ptr_val(ptr_in));

    if (i < NQ4) {
        float4 v = __ldcs(&queue4[i]);
        __stcs(&contf4[2 * NB4 + i], v);      // cont_features queue part
        int row = i >> 5;                     // DD/4 = 32 float4 per row
        if (row >= ptrc && row < ptrc + BB) { // enqueue window -> k row
            v = __ldcs(&k4[(row - ptrc) * 32 + (i & 31)]);
        }
        __stcs(&outq4[i], v);                 // new_queue
    }
    if (i < NB4) {
        float4 vq = __ldcs(&q4[i]);
        float4 vk = __ldcs(&k4[i]);
        __stcs(&contf4[i], vq);
        __stcs(&contf4[NB4 + i], vk);
    }
    if (i < QQ) {
        float v = __ldcs(&qp[i]);
        __stcs(&contl[2 * BB + i], v);        // cont_labels tail
        if (i < ptrc || i >= ptrc + BB)
            __stcs(&outqp[i], v);             // new_queue_pseudo (outside window)
    }
}

// ---------------------------------------------------------------------------
// Kernel 6: labels epilogue (tiny) — depends only on classfy
// ---------------------------------------------------------------------------
__global__ __launch_bounds__(256) void labels_kernel(
    const int* __restrict__ labels, const void* __restrict__ ptr_in,
    float* __restrict__ cont_labels, float* __restrict__ new_qp,
    float* __restrict__ new_ptr_out)
{
    const int ptr = load_ptr_val(ptr_in);
    const int ptrc = clamp_ptr(ptr);
    const int i = blockIdx.x * blockDim.x + threadIdx.x;
    if (i < BB) {
        float lab = (float)labels[i];
        cont_labels[i] = lab;
        cont_labels[BB + i] = lab;
        new_qp[ptrc + i] = lab;
    }
    if (i == 0) new_ptr_out[0] = (float)((ptr + BB) % QQ);
}

// ---------------------------------------------------------------------------
// persistent streams/events (host resources only; created once)
// ---------------------------------------------------------------------------
static bool        g_res_init = false;
static cudaStream_t g_s1, g_s2;
static cudaEvent_t  g_evRoot, g_evB, g_evD;

extern "C" void kernel_launch(void* const* d_in, const int* in_sizes, int n_in,
                              void* d_out, int out_size)
{
    const float* q       = (const float*)d_in[0];
    const float* k       = (const float*)d_in[1];
    const float* logits  = (const float*)d_in[2];
    const float* plabel  = (const float*)d_in[3];
    const float* protos  = (const float*)d_in[4];
    const float* queue   = (const float*)d_in[5];
    const float* queuep  = (const float*)d_in[6];
    const void*  ptr_in  = d_in[7];

    float* out = (float*)d_out;
    float* out_classfy = out + OFF_CLASSFY;
    float* out_cluster = out + OFF_CLUSTER;
    float* out_contf   = out + OFF_CONTF;
    float* out_contl   = out + OFF_CONTL;
    float* out_proto   = out + OFF_PROTO;
    float* out_queue   = out + OFF_QUEUE;
    float* out_qp      = out + OFF_QP;
    float* out_ptr     = out + OFF_PTR;

    float* logits_prot;
    cudaGetSymbolAddress((void**)&logits_prot, g_logits);
    int* labels;
    cudaGetSymbolAddress((void**)&labels, g_labels);

    if (!g_res_init) {
        cudaStreamCreateWithFlags(&g_s1, cudaStreamNonBlocking);
        cudaStreamCreateWithFlags(&g_s2, cudaStreamNonBlocking);
        cudaEventCreateWithFlags(&g_evRoot, cudaEventDisableTiming);
        cudaEventCreateWithFlags(&g_evB, cudaEventDisableTiming);
        cudaEventCreateWithFlags(&g_evD, cudaEventDisableTiming);
        g_res_init = true;
    }

    cudaStream_t s0 = 0;

    // fork
    cudaEventRecord(g_evRoot, s0);
    cudaStreamWaitEvent(g_s1, g_evRoot, 0);
    cudaStreamWaitEvent(g_s2, g_evRoot, 0);

    // ---- chain A (s0): classfy -> labels epilogue -> proto ----
    classfy_kernel<<<BB, 256, 0, s0>>>(
        (const float4*)logits, (const float4*)plabel,
        (float4*)out_classfy, labels);
    labels_kernel<<<(BB + 255) / 256, 256, 0, s0>>>(
        labels, ptr_in, out_contl, out_qp, out_ptr);
    proto_kernel<<<CC, 128, 0, s0>>>(q, protos, labels, out_proto);

    // ---- chain B (s1): gemm -> cluster softmax ----
    {
        dim3 ggrid((CC + TBN - 1) / TBN, BB / TBM);
        gemm_tf32_kernel<<<ggrid, 256, 0, g_s1>>>(q, protos, logits_prot);
        cluster_softmax_kernel<<<BB, 256, 0, g_s1>>>(
            (const float4*)logits_prot, (float4*)out_cluster);
        cudaEventRecord(g_evB, g_s1);
    }

    // ---- chain C (s2): bulk dup (+ k scatter) ----
    {
        int nthreads = QQ * DD / 4;
        bulkdup_kernel<<<(nthreads + 255) / 256, 256, 0, g_s2>>>(
            (const float4*)q, (const float4*)k, (const float4*)queue, queuep,
            ptr_in, (float4*)out_contf, (float4*)out_queue, out_qp, out_contl);
        cudaEventRecord(g_evD, g_s2);
    }

    // join
    cudaStreamWaitEvent(s0, g_evB, 0);
    cudaStreamWaitEvent(s0, g_evD, 0);
}

// round 4
// speedup vs baseline: 1.0844x; 1.0844x over previous
#include <cuda_runtime.h>
#include <cuda_bf16.h>
#include <math.h>
#include <stdint.h>

// Problem constants
#define BB 4096     // batch
#define CC 1000     // classes
#define DD 128      // feature dim
#define QQ 65536    // queue length
#define PROTO_M 0.99f

// ---- output layout (flat float32 concat, reference return order) ----
static const size_t OFF_CLASSFY = 0;
static const size_t OFF_CLUSTER = (size_t)BB * CC;
static const size_t OFF_CONTF   = OFF_CLUSTER + (size_t)BB * CC;
static const size_t OFF_CONTL   = OFF_CONTF + (size_t)(2 * BB + QQ) * DD;
static const size_t OFF_PROTO   = OFF_CONTL + (size_t)(2 * BB + QQ);
static const size_t OFF_QUEUE   = OFF_PROTO + (size_t)CC * DD;
static const size_t OFF_QP      = OFF_QUEUE + (size_t)QQ * DD;
static const size_t OFF_PTR     = OFF_QP + (size_t)QQ;

// scratch (no allocations allowed -> device globals)
__device__ float g_logits[(size_t)BB * CC];
__device__ int   g_labels[BB];

// ---------------------------------------------------------------------------
// ptr decode (int32 or float32 encoding) + dynamic_update_slice clamp
// ---------------------------------------------------------------------------
__device__ __forceinline__ int load_ptr_val(const void* p)
{
    int iv = *(const int*)p;
    if (iv >= 0 && iv <= QQ) return iv;       // stored as int32
    float fv = *(const float*)p;              // stored as float32
    return (int)fv;
}
__device__ __forceinline__ int clamp_ptr(int ptr)
{
    int ptrc = ptr;
    if (ptrc < 0) ptrc = 0;
    if (ptrc > QQ - BB) ptrc = QQ - BB;
    return ptrc;
}

// ---------------------------------------------------------------------------
// Kernel 1: classfy softmax + argmax(softmax*plabel) + labels epilogue fused.
// One block per row b; thread t (<250) owns cols [4t, 4t+4).
// ---------------------------------------------------------------------------
__global__ __launch_bounds__(256) void classfy_kernel(
    const float4* __restrict__ logits4, const float4* __restrict__ plabel4,
    const void* __restrict__ ptr_in,
    float4* __restrict__ out4, int* __restrict__ labels,
    float* __restrict__ cont_labels, float* __restrict__ new_qp,
    float* __restrict__ new_ptr_out)
{
    const int b = blockIdx.x;
    const int tid = threadIdx.x;
    const int RF4 = CC / 4;                 // 250
    const bool act = tid < RF4;

    float4 l = make_float4(-1e30f, -1e30f, -1e30f, -1e30f);
    if (act) l = logits4[(size_t)b * RF4 + tid];

    __shared__ float s0[8];
    __shared__ float s1[8];
    __shared__ float sv[8];
    __shared__ int   si[8];

    float mx = fmaxf(fmaxf(l.x, l.y), fmaxf(l.z, l.w));
#pragma unroll
    for (int o = 16; o; o >>= 1) mx = fmaxf(mx, __shfl_xor_sync(0xffffffffu, mx, o));
    if ((tid & 31) == 0) s0[tid >> 5] = mx;
    __syncthreads();
    if (tid < 32) {
        float v = (tid < 8) ? s0[tid] : -1e30f;
#pragma unroll
        for (int o = 4; o; o >>= 1) v = fmaxf(v, __shfl_xor_sync(0xffffffffu, v, o));
        if (tid == 0) s0[0] = v;
    }
    __syncthreads();
    mx = s0[0];

    float4 e;
    e.x = __expf(l.x - mx); e.y = __expf(l.y - mx);
    e.z = __expf(l.z - mx); e.w = __expf(l.w - mx);
    float sum = act ? (e.x + e.y + e.z + e.w) : 0.f;
#pragma unroll
    for (int o = 16; o; o >>= 1) sum += __shfl_xor_sync(0xffffffffu, sum, o);
    if ((tid & 31) == 0) s1[tid >> 5] = sum;
    __syncthreads();
    if (tid < 32) {
        float v = (tid < 8) ? s1[tid] : 0.f;
#pragma unroll
        for (int o = 4; o; o >>= 1) v += __shfl_xor_sync(0xffffffffu, v, o);
        if (tid == 0) s1[0] = v;
    }
    __syncthreads();
    const float inv = 1.0f / s1[0];

    float bv = -1.0f;
    int bi = 0x7fffffff;
    if (act) {
        float4 p = plabel4[(size_t)b * RF4 + tid];
        float4 o;
        o.x = e.x * inv; o.y = e.y * inv; o.z = e.z * inv; o.w = e.w * inv;
        out4[(size_t)b * RF4 + tid] = o;
        float v0 = o.x * p.x, v1 = o.y * p.y, v2 = o.z * p.z, v3 = o.w * p.w;
        bv = v0; bi = 4 * tid;
        if (v1 > bv) { bv = v1; bi = 4 * tid + 1; }
        if (v2 > bv) { bv = v2; bi = 4 * tid + 2; }
        if (v3 > bv) { bv = v3; bi = 4 * tid + 3; }
    }
#pragma unroll
    for (int o = 16; o; o >>= 1) {
        float ov = __shfl_xor_sync(0xffffffffu, bv, o);
        int   oi = __shfl_xor_sync(0xffffffffu, bi, o);
        if (ov > bv || (ov == bv && oi < bi)) { bv = ov; bi = oi; }
    }
    if ((tid & 31) == 0) { sv[tid >> 5] = bv; si[tid >> 5] = bi; }
    __syncthreads();
    if (tid == 0) {
        float v = sv[0]; int i = si[0];
#pragma unroll
        for (int u = 1; u < 8; u++) {
            if (sv[u] > v || (sv[u] == v && si[u] < i)) { v = sv[u]; i = si[u]; }
        }
        labels[b] = i;
        // fused labels epilogue
        const int ptr = load_ptr_val(ptr_in);
        const int ptrc = clamp_ptr(ptr);
        float lab = (float)i;
        cont_labels[b] = lab;
        cont_labels[BB + b] = lab;
        new_qp[ptrc + b] = lab;
        if (b == 0) new_ptr_out[0] = (float)((ptr + BB) % QQ);
    }
}

// ---------------------------------------------------------------------------
// Kernel 2: logits = q @ protos^T, tf32 tensor cores.
// BM=64, BN=128, full K=128 resident in dynamic smem (load once, no mid-sync).
// 8 warps (2m x 4n), warp tile 32x32, 8 mma per warp k-step.
// smem layout: within each 8-col group, logical col c stored at 2*(c&3)+(c>>2)
// so fragment cols (tig, tig+4) are one aligned LDS.64.
// ---------------------------------------------------------------------------
__device__ __forceinline__ uint32_t f32_to_tf32(float f)
{
    uint32_t r;
    asm volatile("cvt.rna.tf32.f32 %0, %1;" : "=r"(r) : "f"(f));
    return r;
}

__device__ __forceinline__ void mma_tf32(float c[4],
    uint32_t a0, uint32_t a1, uint32_t a2, uint32_t a3,
    uint32_t b0, uint32_t b1)
{
    asm volatile(
        "mma.sync.aligned.m16n8k8.row.col.f32.tf32.tf32.f32 "
        "{%0,%1,%2,%3}, {%4,%5,%6,%7}, {%8,%9}, {%0,%1,%2,%3};"
        : "+f"(c[0]), "+f"(c[1]), "+f"(c[2]), "+f"(c[3])
        : "r"(a0), "r"(a1), "r"(a2), "r"(a3), "r"(b0), "r"(b1));
}

#define TBM 64
#define TBN 128
#define LDP (DD + 4)   // row stride in words (132)
#define GEMM_SMEM_BYTES ((TBM + TBN) * LDP * 4)   // 101,376 bytes

__global__ __launch_bounds__(256) void gemm_tf32_kernel(
    const float* __restrict__ Aq, const float* __restrict__ Bp,
    float* __restrict__ Cout)
{
    extern __shared__ uint32_t smem[];
    uint32_t* As = smem;                 // [TBM][LDP]
    uint32_t* Bs = smem + TBM * LDP;     // [TBN][LDP]

    const int tid  = threadIdx.x;
    const int w    = tid >> 5;
    const int lane = tid & 31;
    const int wm   = w & 1;       // 2 m-warps of 32 rows
    const int wn   = w >> 1;      // 4 n-warps of 32 cols
    const int g    = lane >> 2;   // 0..7
    const int tig  = lane & 3;    // 0..3
    const int m0   = blockIdx.y * TBM;
    const int n0   = blockIdx.x * TBN;

    // ---- load A(64x128) + B(128x128) once: 3072 (row, 8col-group) slots ----
#pragma unroll
    for (int it = 0; it < 12; it++) {
        int slot = it * 256 + tid;
        float4 lo, hi;
        uint32_t* dst;
        if (slot < TBM * 16) {
            int r = slot >> 4, gp = slot & 15;
            const float* src = Aq + (size_t)(m0 + r) * DD + gp * 8;
            lo = *(const float4*)src;
            hi = *(const float4*)(src + 4);
            dst = As + r * LDP + gp * 8;
        } else {
            int s = slot - TBM * 16;
            int r = s >> 4, gp = s & 15;
            int n = n0 + r;
            if (n < CC) {
                const float* src = Bp + (size_t)n * DD + gp * 8;
                lo = *(const float4*)src;
                hi = *(const float4*)(src + 4);
            } else {
                lo = make_float4(0.f, 0.f, 0.f, 0.f);
                hi = lo;
            }
            dst = Bs + r * LDP + gp * 8;
        }
        // interleave: phys = (c0,c4,c1,c5, c2,c6,c3,c7)
        uint4 o0, o1;
        o0.x = f32_to_tf32(lo.x); o0.y = f32_to_tf32(hi.x);
        o0.z = f32_to_tf32(lo.y); o0.w = f32_to_tf32(hi.y);
        o1.x = f32_to_tf32(lo.z); o1.y = f32_to_tf32(hi.z);
        o1.z = f32_to_tf32(lo.w); o1.w = f32_to_tf32(hi.w);
        *(uint4*)dst = o0;
        *(uint4*)(dst + 4) = o1;
    }
    __syncthreads();

    float c[2][4][4];
#pragma unroll
    for (int mt = 0; mt < 2; mt++)
#pragma unroll
        for (int nt = 0; nt < 4; nt++)
#pragma unroll
            for (int i = 0; i < 4; i++) c[mt][nt][i] = 0.f;

    const int rbase = wm * 32;
    const int cbase = wn * 32;

#pragma unroll
    for (int ks = 0; ks < DD / 8; ks++) {
        const int k0 = ks * 8;
        uint2 afr[2][2];   // [mt][row half]: .x = col tig, .y = col tig+4
#pragma unroll
        for (int mt = 0; mt < 2; mt++) {
            int rb = rbase + mt * 16 + g;
            afr[mt][0] = *(const uint2*)(As + rb * LDP + k0 + 2 * tig);
            afr[mt][1] = *(const uint2*)(As + (rb + 8) * LDP + k0 + 2 * tig);
        }
        uint2 bfr[4];
#pragma unroll
        for (int nt = 0; nt < 4; nt++) {
            int cb = cbase + nt * 8 + g;
            bfr[nt] = *(const uint2*)(Bs + cb * LDP + k0 + 2 * tig);
        }
#pragma unroll
        for (int mt = 0; mt < 2; mt++)
#pragma unroll
            for (int nt = 0; nt < 4; nt++)
                mma_tf32(c[mt][nt],
                         afr[mt][0].x, afr[mt][1].x, afr[mt][0].y, afr[mt][1].y,
                         bfr[nt].x, bfr[nt].y);
    }

    // store
#pragma unroll
    for (int mt = 0; mt < 2; mt++) {
#pragma unroll
        for (int nt = 0; nt < 4; nt++) {
            int m = m0 + rbase + mt * 16 + g;
            int n = n0 + cbase + nt * 8 + 2 * tig;
            if (n < CC) {
                *(float2*)(Cout + (size_t)m * CC + n) =
                    make_float2(c[mt][nt][0], c[mt][nt][1]);
                *(float2*)(Cout + (size_t)(m + 8) * CC + n) =
                    make_float2(c[mt][nt][2], c[mt][nt][3]);
            }
        }
    }
}

// ---------------------------------------------------------------------------
// Kernel 3: cluster softmax. Logits are unit-vector dot products in [-1,1],
// so no max-subtraction pass is needed (exp cannot overflow).
// ---------------------------------------------------------------------------
__global__ __launch_bounds__(256) void cluster_softmax_kernel(
    const float4* __restrict__ logits4, float4* __restrict__ out4)
{
    const int b = blockIdx.x;
    const int tid = threadIdx.x;
    const int RF4 = CC / 4;
    const bool act = tid < RF4;

    float4 l = make_float4(0.f, 0.f, 0.f, 0.f);
    if (act) l = logits4[(size_t)b * RF4 + tid];

    __shared__ float s1[8];

    float4 e;
    e.x = __expf(l.x); e.y = __expf(l.y);
    e.z = __expf(l.z); e.w = __expf(l.w);
    float sum = act ? (e.x + e.y + e.z + e.w) : 0.f;
#pragma unroll
    for (int o = 16; o; o >>= 1) sum += __shfl_xor_sync(0xffffffffu, sum, o);
    if ((tid & 31) == 0) s1[tid >> 5] = sum;
    __syncthreads();
    if (tid < 32) {
        float v = (tid < 8) ? s1[tid] : 0.f;
#pragma unroll
        for (int o = 4; o; o >>= 1) v += __shfl_xor_sync(0xffffffffu, v, o);
        if (tid == 0) s1[0] = v;
    }
    __syncthreads();
    const float inv = 1.0f / s1[0];
    if (act) {
        float4 o;
        o.x = e.x * inv; o.y = e.y * inv; o.z = e.z * inv; o.w = e.w * inv;
        out4[(size_t)b * RF4 + tid] = o;
    }
}

// ---------------------------------------------------------------------------
// Kernel 4: prototype scatter-EMA + l2norm. One block (128 thr) per class.
// Hillis-Steele parallel prefix over per-thread match counts.
// ---------------------------------------------------------------------------
__global__ __launch_bounds__(128) void proto_kernel(
    const float* __restrict__ q, const float* __restrict__ protos,
    const int* __restrict__ labels, float* __restrict__ out)
{
    const int c = blockIdx.x;
    const int t = threadIdx.x;

    __shared__ int sc[128];
    __shared__ int idxbuf[BB];
    __shared__ float ws[4];

    const int base = t * 32;
    int cnt = 0;
#pragma unroll 8
    for (int j = 0; j < 32; j++) if (__ldg(&labels[base + j]) == c) cnt++;
    sc[t] = cnt;
    __syncthreads();
    // inclusive scan (Hillis-Steele)
#pragma unroll
    for (int d = 1; d < 128; d <<= 1) {
        int v = (t >= d) ? sc[t - d] : 0;
        __syncthreads();
        sc[t] += v;
        __syncthreads();
    }
    const int total = sc[127];
    int w = sc[t] - cnt;   // exclusive offset
#pragma unroll 8
    for (int j = 0; j < 32; j++) {
        int i = base + j;
        if (__ldg(&labels[i]) == c) idxbuf[w++] = i;
    }
    __syncthreads();

    float acc = protos[(size_t)c * DD + t];
    for (int j = 0; j < total; j++) {
        acc = PROTO_M * acc + (1.0f - PROTO_M) * q[(size_t)idxbuf[j] * DD + t];
    }
    float s = acc * acc;
#pragma unroll
    for (int o = 16; o; o >>= 1) s += __shfl_xor_sync(0xffffffffu, s, o);
    if ((t & 31) == 0) ws[t >> 5] = s;
    __syncthreads();
    float tot = ws[0] + ws[1] + ws[2] + ws[3];
    float nrm = sqrtf(tot);
    float inv = 1.0f / fmaxf(nrm, 1e-12f);
    out[(size_t)c * DD + t] = acc * inv;
}

// ---------------------------------------------------------------------------
// Kernel 5: fused bulk dup + k-row scatter (streaming hints; no reuse).
// new_qp slots in [ptrc, ptrc+B) are owned by classfy's fused epilogue.
// ---------------------------------------------------------------------------
__global__ __launch_bounds__(256) void bulkdup_kernel(
    const float4* __restrict__ q4, const float4* __restrict__ k4,
    const float4* __restrict__ queue4, const float* __restrict__ qp,
    const void* __restrict__ ptr_in,
    float4* __restrict__ contf4, float4* __restrict__ outq4,
    float* __restrict__ outqp, float* __restrict__ contl)
{
    const int i = blockIdx.x * blockDim.x + threadIdx.x;
    const int NQ4 = QQ * DD / 4;   // 2,097,152
    const int NB4 = BB * DD / 4;   // 131,072
    const int ptrc = clamp_ptr(load_ptr_val(ptr_in));

    if (i < NQ4) {
        float4 v = __ldcs(&queue4[i]);
        __stcs(&contf4[2 * NB4 + i], v);      // cont_features queue part
        int row = i >> 5;                     // DD/4 = 32 float4 per row
        if (row >= ptrc && row < ptrc + BB) { // enqueue window -> k row
            v = __ldcs(&k4[(row - ptrc) * 32 + (i & 31)]);
        }
        __stcs(&outq4[i], v);                 // new_queue
    }
    if (i < NB4) {
        float4 vq = __ldcs(&q4[i]);
        float4 vk = __ldcs(&k4[i]);
        __stcs(&contf4[i], vq);
        __stcs(&contf4[NB4 + i], vk);
    }
    if (i < QQ) {
        float v = __ldcs(&qp[i]);
        __stcs(&contl[2 * BB + i], v);        // cont_labels tail
        if (i < ptrc || i >= ptrc + BB)
            __stcs(&outqp[i], v);             // new_queue_pseudo (outside window)
    }
}

// ---------------------------------------------------------------------------
static bool g_init = false;

extern "C" void kernel_launch(void* const* d_in, const int* in_sizes, int n_in,
                              void* d_out, int out_size)
{
    const float* q       = (const float*)d_in[0];
    const float* k       = (const float*)d_in[1];
    const float* logits  = (const float*)d_in[2];
    const float* plabel  = (const float*)d_in[3];
    const float* protos  = (const float*)d_in[4];
    const float* queue   = (const float*)d_in[5];
    const float* queuep  = (const float*)d_in[6];
    const void*  ptr_in  = d_in[7];

    float* out = (float*)d_out;
    float* out_classfy = out + OFF_CLASSFY;
    float* out_cluster = out + OFF_CLUSTER;
    float* out_contf   = out + OFF_CONTF;
    float* out_contl   = out + OFF_CONTL;
    float* out_proto   = out + OFF_PROTO;
    float* out_queue   = out + OFF_QUEUE;
    float* out_qp      = out + OFF_QP;
    float* out_ptr     = out + OFF_PTR;

    float* logits_prot;
    cudaGetSymbolAddress((void**)&logits_prot, g_logits);
    int* labels;
    cudaGetSymbolAddress((void**)&labels, g_labels);

    if (!g_init) {
        cudaFuncSetAttribute(gemm_tf32_kernel,
                             cudaFuncAttributeMaxDynamicSharedMemorySize,
                             GEMM_SMEM_BYTES);
        g_init = true;
    }

    cudaStream_t s = 0;

    // 1) classfy softmax + pseudo labels + labels epilogue (fused)
    classfy_kernel<<<BB, 256, 0, s>>>(
        (const float4*)logits, (const float4*)plabel, ptr_in,
        (float4*)out_classfy, labels, out_contl, out_qp, out_ptr);

    // 2) cluster logits GEMM (tf32) -> scratch
    {
        dim3 ggrid((CC + TBN - 1) / TBN, BB / TBM);   // 8 x 64
        gemm_tf32_kernel<<<ggrid, 256, GEMM_SMEM_BYTES, s>>>(q, protos, logits_prot);
    }

    // 3) cluster softmax (no-max variant: inputs bounded by 1)
    cluster_softmax_kernel<<<BB, 256, 0, s>>>(
        (const float4*)logits_prot, (float4*)out_cluster);

    // 4) fused bulk copies + k scatter
    {
        int nthreads = QQ * DD / 4;
        bulkdup_kernel<<<(nthreads + 255) / 256, 256, 0, s>>>(
            (const float4*)q, (const float4*)k, (const float4*)queue, queuep,
            ptr_in, (float4*)out_contf, (float4*)out_queue, out_qp, out_contl);
    }

    // 5) prototype EMA update
    proto_kernel<<<CC, 128, 0, s>>>(q, protos, labels, out_proto);
}

// round 5
// speedup vs baseline: 1.3466x; 1.2418x over previous
#include <cuda_runtime.h>
#include <cuda_bf16.h>
#include <math.h>
#include <stdint.h>

// Problem constants
#define BB 4096     // batch
#define CC 1000     // classes
#define DD 128      // feature dim
#define QQ 65536    // queue length
#define PROTO_M 0.99f

// ---- output layout (flat float32 concat, reference return order) ----
static const size_t OFF_CLASSFY = 0;
static const size_t OFF_CLUSTER = (size_t)BB * CC;
static const size_t OFF_CONTF   = OFF_CLUSTER + (size_t)BB * CC;
static const size_t OFF_CONTL   = OFF_CONTF + (size_t)(2 * BB + QQ) * DD;
static const size_t OFF_PROTO   = OFF_CONTL + (size_t)(2 * BB + QQ);
static const size_t OFF_QUEUE   = OFF_PROTO + (size_t)CC * DD;
static const size_t OFF_QP      = OFF_QUEUE + (size_t)QQ * DD;
static const size_t OFF_PTR     = OFF_QP + (size_t)QQ;

// scratch (no allocations allowed -> device globals)
__device__ float g_logits[(size_t)BB * CC];  // holds exp(logit) after gemm
__device__ float g_psum[(size_t)BB * 8];     // per-(row, n-block) exp partial sums
__device__ int   g_labels[BB];

// ---------------------------------------------------------------------------
// ptr decode (int32 or float32 encoding) + dynamic_update_slice clamp
// ---------------------------------------------------------------------------
__device__ __forceinline__ int load_ptr_val(const void* p)
{
    int iv = *(const int*)p;
    if (iv >= 0 && iv <= QQ) return iv;       // stored as int32
    float fv = *(const float*)p;              // stored as float32
    return (int)fv;
}
__device__ __forceinline__ int clamp_ptr(int ptr)
{
    int ptrc = ptr;
    if (ptrc < 0) ptrc = 0;
    if (ptrc > QQ - BB) ptrc = QQ - BB;
    return ptrc;
}

// ---------------------------------------------------------------------------
// Kernel 1: classfy softmax + argmax(softmax*plabel) + labels epilogue fused.
// ---------------------------------------------------------------------------
__global__ __launch_bounds__(256) void classfy_kernel(
    const float4* __restrict__ logits4, const float4* __restrict__ plabel4,
    const void* __restrict__ ptr_in,
    float4* __restrict__ out4, int* __restrict__ labels,
    float* __restrict__ cont_labels, float* __restrict__ new_qp,
    float* __restrict__ new_ptr_out)
{
    const int b = blockIdx.x;
    const int tid = threadIdx.x;
    const int RF4 = CC / 4;                 // 250
    const bool act = tid < RF4;

    float4 l = make_float4(-1e30f, -1e30f, -1e30f, -1e30f);
    if (act) l = logits4[(size_t)b * RF4 + tid];

    __shared__ float s0[8];
    __shared__ float s1[8];
    __shared__ float sv[8];
    __shared__ int   si[8];

    float mx = fmaxf(fmaxf(l.x, l.y), fmaxf(l.z, l.w));
#pragma unroll
    for (int o = 16; o; o >>= 1) mx = fmaxf(mx, __shfl_xor_sync(0xffffffffu, mx, o));
    if ((tid & 31) == 0) s0[tid >> 5] = mx;
    __syncthreads();
    if (tid < 32) {
        float v = (tid < 8) ? s0[tid] : -1e30f;
#pragma unroll
        for (int o = 4; o; o >>= 1) v = fmaxf(v, __shfl_xor_sync(0xffffffffu, v, o));
        if (tid == 0) s0[0] = v;
    }
    __syncthreads();
    mx = s0[0];

    float4 e;
    e.x = __expf(l.x - mx); e.y = __expf(l.y - mx);
    e.z = __expf(l.z - mx); e.w = __expf(l.w - mx);
    float sum = act ? (e.x + e.y + e.z + e.w) : 0.f;
#pragma unroll
    for (int o = 16; o; o >>= 1) sum += __shfl_xor_sync(0xffffffffu, sum, o);
    if ((tid & 31) == 0) s1[tid >> 5] = sum;
    __syncthreads();
    if (tid < 32) {
        float v = (tid < 8) ? s1[tid] : 0.f;
#pragma unroll
        for (int o = 4; o; o >>= 1) v += __shfl_xor_sync(0xffffffffu, v, o);
        if (tid == 0) s1[0] = v;
    }
    __syncthreads();
    const float inv = 1.0f / s1[0];

    float bv = -1.0f;
    int bi = 0x7fffffff;
    if (act) {
        float4 p = plabel4[(size_t)b * RF4 + tid];
        float4 o;
        o.x = e.x * inv; o.y = e.y * inv; o.z = e.z * inv; o.w = e.w * inv;
        out4[(size_t)b * RF4 + tid] = o;
        float v0 = o.x * p.x, v1 = o.y * p.y, v2 = o.z * p.z, v3 = o.w * p.w;
        bv = v0; bi = 4 * tid;
        if (v1 > bv) { bv = v1; bi = 4 * tid + 1; }
        if (v2 > bv) { bv = v2; bi = 4 * tid + 2; }
        if (v3 > bv) { bv = v3; bi = 4 * tid + 3; }
    }
#pragma unroll
    for (int o = 16; o; o >>= 1) {
        float ov = __shfl_xor_sync(0xffffffffu, bv, o);
        int   oi = __shfl_xor_sync(0xffffffffu, bi, o);
        if (ov > bv || (ov == bv && oi < bi)) { bv = ov; bi = oi; }
    }
    if ((tid & 31) == 0) { sv[tid >> 5] = bv; si[tid >> 5] = bi; }
    __syncthreads();
    if (tid == 0) {
        float v = sv[0]; int i = si[0];
#pragma unroll
        for (int u = 1; u < 8; u++) {
            if (sv[u] > v || (sv[u] == v && si[u] < i)) { v = sv[u]; i = si[u]; }
        }
        labels[b] = i;
        const int ptr = load_ptr_val(ptr_in);
        const int ptrc = clamp_ptr(ptr);
        float lab = (float)i;
        cont_labels[b] = lab;
        cont_labels[BB + b] = lab;
        new_qp[ptrc + b] = lab;
        if (b == 0) new_ptr_out[0] = (float)((ptr + BB) % QQ);
    }
}

// ---------------------------------------------------------------------------
// Kernel 2: exp(q @ protos^T) + per-(row, n-block) partial sums.
// tf32 tensor cores, BM=64 BN=128, full K resident, LDS.64 fragments.
// ---------------------------------------------------------------------------
__device__ __forceinline__ uint32_t f32_to_tf32(float f)
{
    uint32_t r;
    asm volatile("cvt.rna.tf32.f32 %0, %1;" : "=r"(r) : "f"(f));
    return r;
}

__device__ __forceinline__ void mma_tf32(float c[4],
    uint32_t a0, uint32_t a1, uint32_t a2, uint32_t a3,
    uint32_t b0, uint32_t b1)
{
    asm volatile(
        "mma.sync.aligned.m16n8k8.row.col.f32.tf32.tf32.f32 "
        "{%0,%1,%2,%3}, {%4,%5,%6,%7}, {%8,%9}, {%0,%1,%2,%3};"
        : "+f"(c[0]), "+f"(c[1]), "+f"(c[2]), "+f"(c[3])
        : "r"(a0), "r"(a1), "r"(a2), "r"(a3), "r"(b0), "r"(b1));
}

#define TBM 64
#define TBN 128
#define LDP (DD + 4)   // row stride in words (132)
#define GEMM_SMEM_BYTES ((TBM + TBN) * LDP * 4)   // 101,376 bytes

__global__ __launch_bounds__(256) void gemm_tf32_kernel(
    const float* __restrict__ Aq, const float* __restrict__ Bp,
    float* __restrict__ Eout, float* __restrict__ psum)
{
    extern __shared__ uint32_t smem[];
    uint32_t* As = smem;                 // [TBM][LDP]
    uint32_t* Bs = smem + TBM * LDP;     // [TBN][LDP]
    __shared__ float smem_part[TBM][4];

    const int tid  = threadIdx.x;
    const int w    = tid >> 5;
    const int lane = tid & 31;
    const int wm   = w & 1;
    const int wn   = w >> 1;
    const int g    = lane >> 2;
    const int tig  = lane & 3;
    const int m0   = blockIdx.y * TBM;
    const int n0   = blockIdx.x * TBN;

    // ---- load A(64x128) + B(128x128) once ----
#pragma unroll
    for (int it = 0; it < 12; it++) {
        int slot = it * 256 + tid;
        float4 lo, hi;
        uint32_t* dst;
        if (slot < TBM * 16) {
            int r = slot >> 4, gp = slot & 15;
            const float* src = Aq + (size_t)(m0 + r) * DD + gp * 8;
            lo = *(const float4*)src;
            hi = *(const float4*)(src + 4);
            dst = As + r * LDP + gp * 8;
        } else {
            int s = slot - TBM * 16;
            int r = s >> 4, gp = s & 15;
            int n = n0 + r;
            if (n < CC) {
                const float* src = Bp + (size_t)n * DD + gp * 8;
                lo = *(const float4*)src;
                hi = *(const float4*)(src + 4);
            } else {
                lo = make_float4(0.f, 0.f, 0.f, 0.f);
                hi = lo;
            }
            dst = Bs + r * LDP + gp * 8;
        }
        uint4 o0, o1;
        o0.x = f32_to_tf32(lo.x); o0.y = f32_to_tf32(hi.x);
        o0.z = f32_to_tf32(lo.y); o0.w = f32_to_tf32(hi.y);
        o1.x = f32_to_tf32(lo.z); o1.y = f32_to_tf32(hi.z);
        o1.z = f32_to_tf32(lo.w); o1.w = f32_to_tf32(hi.w);
        *(uint4*)dst = o0;
        *(uint4*)(dst + 4) = o1;
    }
    __syncthreads();

    float c[2][4][4];
#pragma unroll
    for (int mt = 0; mt < 2; mt++)
#pragma unroll
        for (int nt = 0; nt < 4; nt++)
#pragma unroll
            for (int i = 0; i < 4; i++) c[mt][nt][i] = 0.f;

    const int rbase = wm * 32;
    const int cbase = wn * 32;

#pragma unroll
    for (int ks = 0; ks < DD / 8; ks++) {
        const int k0 = ks * 8;
        uint2 afr[2][2];
#pragma unroll
        for (int mt = 0; mt < 2; mt++) {
            int rb = rbase + mt * 16 + g;
            afr[mt][0] = *(const uint2*)(As + rb * LDP + k0 + 2 * tig);
            afr[mt][1] = *(const uint2*)(As + (rb + 8) * LDP + k0 + 2 * tig);
        }
        uint2 bfr[4];
#pragma unroll
        for (int nt = 0; nt < 4; nt++) {
            int cb = cbase + nt * 8 + g;
            bfr[nt] = *(const uint2*)(Bs + cb * LDP + k0 + 2 * tig);
        }
#pragma unroll
        for (int mt = 0; mt < 2; mt++)
#pragma unroll
            for (int nt = 0; nt < 4; nt++)
                mma_tf32(c[mt][nt],
                         afr[mt][0].x, afr[mt][1].x, afr[mt][0].y, afr[mt][1].y,
                         bfr[nt].x, bfr[nt].y);
    }

    // ---- epilogue: exp, store, per-row partial sums (deterministic) ----
    float rs[2][2] = {{0.f, 0.f}, {0.f, 0.f}};   // [mt][row half]
#pragma unroll
    for (int mt = 0; mt < 2; mt++) {
#pragma unroll
        for (int nt = 0; nt < 4; nt++) {
            int m = m0 + rbase + mt * 16 + g;
            int n = n0 + cbase + nt * 8 + 2 * tig;
            if (n < CC) {   // CC even, n even -> n+1 < CC too
                float e0 = __expf(c[mt][nt][0]);
                float e1 = __expf(c[mt][nt][1]);
                float e2 = __expf(c[mt][nt][2]);
                float e3 = __expf(c[mt][nt][3]);
                *(float2*)(Eout + (size_t)m * CC + n) = make_float2(e0, e1);
                *(float2*)(Eout + (size_t)(m + 8) * CC + n) = make_float2(e2, e3);
                rs[mt][0] += e0 + e1;
                rs[mt][1] += e2 + e3;
            }
        }
    }
    // reduce across the 4 tig lanes (same g)
#pragma unroll
    for (int o = 1; o <= 2; o <<= 1) {
#pragma unroll
        for (int mt = 0; mt < 2; mt++) {
            rs[mt][0] += __shfl_xor_sync(0xffffffffu, rs[mt][0], o);
            rs[mt][1] += __shfl_xor_sync(0xffffffffu, rs[mt][1], o);
        }
    }
    if (tig == 0) {
#pragma unroll
        for (int mt = 0; mt < 2; mt++) {
            smem_part[rbase + mt * 16 + g][wn]     = rs[mt][0];
            smem_part[rbase + mt * 16 + 8 + g][wn] = rs[mt][1];
        }
    }
    __syncthreads();
    if (tid < TBM) {
        float s = smem_part[tid][0] + smem_part[tid][1]
                + smem_part[tid][2] + smem_part[tid][3];
        psum[(size_t)(m0 + tid) * 8 + blockIdx.x] = s;
    }
}

// ---------------------------------------------------------------------------
// Kernel 3: megatail — role-split single launch:
//   blocks [0, 4096):        bulk dup + k scatter (2 float4 per thread)
//   blocks [4096, 8192):     cluster softmax normalize (one row each)
//   blocks [8192, 9192):     prototype EMA + l2norm (one class each)
// ---------------------------------------------------------------------------
#define NQ4   (QQ * DD / 4)      // 2,097,152
#define HALF4 (NQ4 / 2)          // 1,048,576
#define NB4   (BB * DD / 4)      // 131,072
#define MT_BULK  (HALF4 / 256)   // 4096
#define MT_NORM  BB              // 4096
#define MT_PROTO CC              // 1000
#define MT_GRID  (MT_BULK + MT_NORM + MT_PROTO)

__global__ __launch_bounds__(256) void megatail_kernel(
    const float4* __restrict__ q4, const float4* __restrict__ k4,
    const float4* __restrict__ queue4, const float* __restrict__ qp,
    const void* __restrict__ ptr_in,
    const float4* __restrict__ escratch4, const float* __restrict__ psum,
    const float* __restrict__ qf, const float* __restrict__ protos,
    const int* __restrict__ labels,
    float4* __restrict__ contf4, float4* __restrict__ outq4,
    float* __restrict__ outqp, float* __restrict__ contl,
    float4* __restrict__ cluster4, float* __restrict__ out_proto)
{
    const int bid = blockIdx.x;
    const int tid = threadIdx.x;

    if (bid < MT_BULK) {
        // ---------------- bulk dup role ----------------
        const int ptrc = clamp_ptr(load_ptr_val(ptr_in));
        const int i = bid * 256 + tid;
#pragma unroll
        for (int h = 0; h < 2; h++) {
            int idx = i + h * HALF4;
            float4 v = __ldcs(&queue4[idx]);
            __stcs(&contf4[2 * NB4 + idx], v);       // cont_features queue part
            int row = idx >> 5;                       // 32 float4 per row
            if (row >= ptrc && row < ptrc + BB)
                v = __ldcs(&k4[(row - ptrc) * 32 + (idx & 31)]);
            __stcs(&outq4[idx], v);                   // new_queue
        }
        if (i < NB4) {
            float4 vq = __ldcs(&q4[i]);
            float4 vk = __ldcs(&k4[i]);
            __stcs(&contf4[i], vq);
            __stcs(&contf4[NB4 + i], vk);
        }
        if (i < QQ) {
            float v = __ldcs(&qp[i]);
            __stcs(&contl[2 * BB + i], v);            // cont_labels tail
            if (i < ptrc || i >= ptrc + BB)
                __stcs(&outqp[i], v);                 // new_queue_pseudo
        }
    } else if (bid < MT_BULK + MT_NORM) {
        // ---------------- cluster softmax normalize role ----------------
        const int r = bid - MT_BULK;
        const int RF4 = CC / 4;                       // 250
        float total = 0.f;
#pragma unroll
        for (int j = 0; j < 8; j++) total += psum[(size_t)r * 8 + j];
        const float inv = 1.0f / total;
        if (tid < RF4) {
            float4 e = escratch4[(size_t)r * RF4 + tid];
            e.x *= inv; e.y *= inv; e.z *= inv; e.w *= inv;
            cluster4[(size_t)r * RF4 + tid] = e;
        }
    } else {
        // ---------------- prototype EMA role ----------------
        const int c = bid - MT_BULK - MT_NORM;
        __shared__ int sc[256];
        __shared__ int idxbuf[BB];
        __shared__ float ws[4];

        const int base = tid * 16;
        int cnt = 0;
#pragma unroll 8
        for (int j = 0; j < 16; j++) if (__ldg(&labels[base + j]) == c) cnt++;
        sc[tid] = cnt;
        __syncthreads();
#pragma unroll
        for (int d = 1; d < 256; d <<= 1) {
            int v = (tid >= d) ? sc[tid - d] : 0;
            __syncthreads();
            sc[tid] += v;
            __syncthreads();
        }
        const int total = sc[255];
        int w = sc[tid] - cnt;
#pragma unroll 8
        for (int j = 0; j < 16; j++) {
            int i = base + j;
            if (__ldg(&labels[i]) == c) idxbuf[w++] = i;
        }
        __syncthreads();

        float acc = 0.f;
        if (tid < DD) {
            acc = protos[(size_t)c * DD + tid];
            for (int j = 0; j < total; j++)
                acc = PROTO_M * acc + (1.0f - PROTO_M) * qf[(size_t)idxbuf[j] * DD + tid];
        }
        float s = acc * acc;
#pragma unroll
        for (int o = 16; o; o >>= 1) s += __shfl_xor_sync(0xffffffffu, s, o);
        if (tid < DD && (tid & 31) == 0) ws[tid >> 5] = s;
        __syncthreads();
        if (tid < DD) {
            float tot = ws[0] + ws[1] + ws[2] + ws[3];
            float inv = 1.0f / fmaxf(sqrtf(tot), 1e-12f);
            out_proto[(size_t)c * DD + tid] = acc * inv;
        }
    }
}

// ---------------------------------------------------------------------------
static bool g_init = false;

extern "C" void kernel_launch(void* const* d_in, const int* in_sizes, int n_in,
                              void* d_out, int out_size)
{
    const float* q       = (const float*)d_in[0];
    const float* k       = (const float*)d_in[1];
    const float* logits  = (const float*)d_in[2];
    const float* plabel  = (const float*)d_in[3];
    const float* protos  = (const float*)d_in[4];
    const float* queue   = (const float*)d_in[5];
    const float* queuep  = (const float*)d_in[6];
    const void*  ptr_in  = d_in[7];

    float* out = (float*)d_out;
    float* out_classfy = out + OFF_CLASSFY;
    float* out_cluster = out + OFF_CLUSTER;
    float* out_contf   = out + OFF_CONTF;
    float* out_contl   = out + OFF_CONTL;
    float* out_proto   = out + OFF_PROTO;
    float* out_queue   = out + OFF_QUEUE;
    float* out_qp      = out + OFF_QP;
    float* out_ptr     = out + OFF_PTR;

    float* escratch;
    cudaGetSymbolAddress((void**)&escratch, g_logits);
    float* psum;
    cudaGetSymbolAddress((void**)&psum, g_psum);
    int* labels;
    cudaGetSymbolAddress((void**)&labels, g_labels);

    if (!g_init) {
        cudaFuncSetAttribute(gemm_tf32_kernel,
                             cudaFuncAttributeMaxDynamicSharedMemorySize,
                             GEMM_SMEM_BYTES);
        g_init = true;
    }

    cudaStream_t s = 0;

    // 1) classfy softmax + pseudo labels + labels epilogue (fused)
    classfy_kernel<<<BB, 256, 0, s>>>(
        (const float4*)logits, (const float4*)plabel, ptr_in,
        (float4*)out_classfy, labels, out_contl, out_qp, out_ptr);

    // 2) exp(q @ protos^T) + partial sums -> scratch
    {
        dim3 ggrid((CC + TBN - 1) / TBN, BB / TBM);   // 8 x 64
        gemm_tf32_kernel<<<ggrid, 256, GEMM_SMEM_BYTES, s>>>(
            q, protos, escratch, psum);
    }

    // 3) megatail: bulkdup + cluster normalize + proto EMA (one launch)
    megatail_kernel<<<MT_GRID, 256, 0, s>>>(
        (const float4*)q, (const float4*)k, (const float4*)queue, queuep,
        ptr_in, (const float4*)escratch, psum, q, protos, labels,
        (float4*)out_contf, (float4*)out_queue, out_qp, out_contl,
        (float4*)out_cluster, out_proto);
}

// round 6
// speedup vs baseline: 1.3830x; 1.0270x over previous
#include <cuda_runtime.h>
#include <cuda_bf16.h>
#include <math.h>
#include <stdint.h>

// Problem constants
#define BB 4096     // batch
#define CC 1000     // classes
#define DD 128      // feature dim
#define QQ 65536    // queue length
#define PROTO_M 0.99f

// ---- output layout (flat float32 concat, reference return order) ----
static const size_t OFF_CLASSFY = 0;
static const size_t OFF_CLUSTER = (size_t)BB * CC;
static const size_t OFF_CONTF   = OFF_CLUSTER + (size_t)BB * CC;
static const size_t OFF_CONTL   = OFF_CONTF + (size_t)(2 * BB + QQ) * DD;
static const size_t OFF_PROTO   = OFF_CONTL + (size_t)(2 * BB + QQ);
static const size_t OFF_QUEUE   = OFF_PROTO + (size_t)CC * DD;
static const size_t OFF_QP      = OFF_QUEUE + (size_t)QQ * DD;
static const size_t OFF_PTR     = OFF_QP + (size_t)QQ;

// scratch (no allocations allowed -> device globals)
__device__ float g_logits[(size_t)BB * CC];  // holds exp(logit) after head
__device__ float g_psum[(size_t)BB * 8];     // per-(row, n-block) exp partial sums
__device__ int   g_labels[BB];

// ---------------------------------------------------------------------------
// ptr decode (int32 or float32 encoding) + dynamic_update_slice clamp
// ---------------------------------------------------------------------------
__device__ __forceinline__ int load_ptr_val(const void* p)
{
    int iv = *(const int*)p;
    if (iv >= 0 && iv <= QQ) return iv;       // stored as int32
    float fv = *(const float*)p;              // stored as float32
    return (int)fv;
}
__device__ __forceinline__ int clamp_ptr(int ptr)
{
    int ptrc = ptr;
    if (ptrc < 0) ptrc = 0;
    if (ptrc > QQ - BB) ptrc = QQ - BB;
    return ptrc;
}

// ---------------------------------------------------------------------------
// tf32 helpers
// ---------------------------------------------------------------------------
__device__ __forceinline__ uint32_t f32_to_tf32(float f)
{
    uint32_t r;
    asm volatile("cvt.rna.tf32.f32 %0, %1;" : "=r"(r) : "f"(f));
    return r;
}

__device__ __forceinline__ void mma_tf32(float c[4],
    uint32_t a0, uint32_t a1, uint32_t a2, uint32_t a3,
    uint32_t b0, uint32_t b1)
{
    asm volatile(
        "mma.sync.aligned.m16n8k8.row.col.f32.tf32.tf32.f32 "
        "{%0,%1,%2,%3}, {%4,%5,%6,%7}, {%8,%9}, {%0,%1,%2,%3};"
        : "+f"(c[0]), "+f"(c[1]), "+f"(c[2]), "+f"(c[3])
        : "r"(a0), "r"(a1), "r"(a2), "r"(a3), "r"(b0), "r"(b1));
}

#define TBM 64
#define TBN 128
#define LDP (DD + 4)   // row stride in words (132)
#define GEMM_SMEM_BYTES ((TBM + TBN) * LDP * 4)   // 101,376 bytes
#define GEMM_BLOCKS ((CC + TBN - 1) / TBN * (BB / TBM))   // 8 * 64 = 512
#define CLS_BLOCKS  (BB / 8)                               // 512

// ---------------------------------------------------------------------------
// gemm role: exp(q @ protos^T) + per-(row, n-block) partial sums
// ---------------------------------------------------------------------------
__device__ void gemm_role(int gb, uint32_t* smem,
    const float* __restrict__ Aq, const float* __restrict__ Bp,
    float* __restrict__ Eout, float* __restrict__ psum)
{
    uint32_t* As = smem;                 // [TBM][LDP]
    uint32_t* Bs = smem + TBM * LDP;     // [TBN][LDP]
    __shared__ float smem_part[TBM][4];

    const int tid  = threadIdx.x;
    const int lane = tid & 31;
    const int w    = tid >> 5;
    const int wm   = w & 1;
    const int wn   = w >> 1;
    const int g    = lane >> 2;
    const int tig  = lane & 3;
    const int bx   = gb & 7;             // 8 n-blocks
    const int by   = gb >> 3;            // 64 m-blocks
    const int m0   = by * TBM;
    const int n0   = bx * TBN;

    // ---- load A(64x128) + B(128x128) once ----
#pragma unroll
    for (int it = 0; it < 12; it++) {
        int slot = it * 256 + tid;
        float4 lo, hi;
        uint32_t* dst;
        if (slot < TBM * 16) {
            int r = slot >> 4, gp = slot & 15;
            const float* src = Aq + (size_t)(m0 + r) * DD + gp * 8;
            lo = *(const float4*)src;
            hi = *(const float4*)(src + 4);
            dst = As + r * LDP + gp * 8;
        } else {
            int s = slot - TBM * 16;
            int r = s >> 4, gp = s & 15;
            int n = n0 + r;
            if (n < CC) {
                const float* src = Bp + (size_t)n * DD + gp * 8;
                lo = *(const float4*)src;
                hi = *(const float4*)(src + 4);
            } else {
                lo = make_float4(0.f, 0.f, 0.f, 0.f);
                hi = lo;
            }
            dst = Bs + r * LDP + gp * 8;
        }
        uint4 o0, o1;
        o0.x = f32_to_tf32(lo.x); o0.y = f32_to_tf32(hi.x);
        o0.z = f32_to_tf32(lo.y); o0.w = f32_to_tf32(hi.y);
        o1.x = f32_to_tf32(lo.z); o1.y = f32_to_tf32(hi.z);
        o1.z = f32_to_tf32(lo.w); o1.w = f32_to_tf32(hi.w);
        *(uint4*)dst = o0;
        *(uint4*)(dst + 4) = o1;
    }
    __syncthreads();

    float c[2][4][4];
#pragma unroll
    for (int mt = 0; mt < 2; mt++)
#pragma unroll
        for (int nt = 0; nt < 4; nt++)
#pragma unroll
            for (int i = 0; i < 4; i++) c[mt][nt][i] = 0.f;

    const int rbase = wm * 32;
    const int cbase = wn * 32;

#pragma unroll
    for (int ks = 0; ks < DD / 8; ks++) {
        const int k0 = ks * 8;
        uint2 afr[2][2];
#pragma unroll
        for (int mt = 0; mt < 2; mt++) {
            int rb = rbase + mt * 16 + g;
            afr[mt][0] = *(const uint2*)(As + rb * LDP + k0 + 2 * tig);
            afr[mt][1] = *(const uint2*)(As + (rb + 8) * LDP + k0 + 2 * tig);
        }
        uint2 bfr[4];
#pragma unroll
        for (int nt = 0; nt < 4; nt++) {
            int cb = cbase + nt * 8 + g;
            bfr[nt] = *(const uint2*)(Bs + cb * LDP + k0 + 2 * tig);
        }
#pragma unroll
        for (int mt = 0; mt < 2; mt++)
#pragma unroll
            for (int nt = 0; nt < 4; nt++)
                mma_tf32(c[mt][nt],
                         afr[mt][0].x, afr[mt][1].x, afr[mt][0].y, afr[mt][1].y,
                         bfr[nt].x, bfr[nt].y);
    }

    // ---- epilogue: exp, store, per-row partial sums (deterministic) ----
    float rs[2][2] = {{0.f, 0.f}, {0.f, 0.f}};
#pragma unroll
    for (int mt = 0; mt < 2; mt++) {
#pragma unroll
        for (int nt = 0; nt < 4; nt++) {
            int m = m0 + rbase + mt * 16 + g;
            int n = n0 + cbase + nt * 8 + 2 * tig;
            if (n < CC) {
                float e0 = __expf(c[mt][nt][0]);
                float e1 = __expf(c[mt][nt][1]);
                float e2 = __expf(c[mt][nt][2]);
                float e3 = __expf(c[mt][nt][3]);
                *(float2*)(Eout + (size_t)m * CC + n) = make_float2(e0, e1);
                *(float2*)(Eout + (size_t)(m + 8) * CC + n) = make_float2(e2, e3);
                rs[mt][0] += e0 + e1;
                rs[mt][1] += e2 + e3;
            }
        }
    }
#pragma unroll
    for (int o = 1; o <= 2; o <<= 1) {
#pragma unroll
        for (int mt = 0; mt < 2; mt++) {
            rs[mt][0] += __shfl_xor_sync(0xffffffffu, rs[mt][0], o);
            rs[mt][1] += __shfl_xor_sync(0xffffffffu, rs[mt][1], o);
        }
    }
    if (tig == 0) {
#pragma unroll
        for (int mt = 0; mt < 2; mt++) {
            smem_part[rbase + mt * 16 + g][wn]     = rs[mt][0];
            smem_part[rbase + mt * 16 + 8 + g][wn] = rs[mt][1];
        }
    }
    __syncthreads();
    if (tid < TBM) {
        float s = smem_part[tid][0] + smem_part[tid][1]
                + smem_part[tid][2] + smem_part[tid][3];
        psum[(size_t)(m0 + tid) * 8 + bx] = s;
    }
}

// ---------------------------------------------------------------------------
// classfy role: warp-per-row softmax + argmax(softmax*plabel) + labels epi.
// No block syncs — pure warp shuffles. 8 rows per block.
// ---------------------------------------------------------------------------
__device__ void classfy_role(int cb,
    const float4* __restrict__ logits4, const float4* __restrict__ plabel4,
    const void* __restrict__ ptr_in,
    float4* __restrict__ out4, int* __restrict__ labels,
    float* __restrict__ cont_labels, float* __restrict__ new_qp,
    float* __restrict__ new_ptr_out)
{
    const int tid  = threadIdx.x;
    const int w    = tid >> 5;
    const int lane = tid & 31;
    const int row  = cb * 8 + w;
    const int RF4  = CC / 4;               // 250
    const float4* lrow = logits4 + (size_t)row * RF4;
    const float4* prow = plabel4 + (size_t)row * RF4;
    float4* orow = out4 + (size_t)row * RF4;

    float4 l[8];
    float mx = -1e30f;
#pragma unroll
    for (int j = 0; j < 8; j++) {
        int c4 = j * 32 + lane;
        if (c4 < RF4) {
            l[j] = lrow[c4];
            mx = fmaxf(mx, fmaxf(fmaxf(l[j].x, l[j].y), fmaxf(l[j].z, l[j].w)));
        } else {
            l[j] = make_float4(-1e30f, -1e30f, -1e30f, -1e30f);
        }
    }
#pragma unroll
    for (int o = 16; o; o >>= 1) mx = fmaxf(mx, __shfl_xor_sync(0xffffffffu, mx, o));

    float sum = 0.f;
#pragma unroll
    for (int j = 0; j < 8; j++) {
        l[j].x = __expf(l[j].x - mx);
        l[j].y = __expf(l[j].y - mx);
        l[j].z = __expf(l[j].z - mx);
        l[j].w = __expf(l[j].w - mx);
        sum += l[j].x + l[j].y + l[j].z + l[j].w;
    }
#pragma unroll
    for (int o = 16; o; o >>= 1) sum += __shfl_xor_sync(0xffffffffu, sum, o);
    const float inv = 1.0f / sum;

    float bv = -1.0f;
    int bi = 0x7fffffff;
#pragma unroll
    for (int j = 0; j < 8; j++) {
        int c4 = j * 32 + lane;
        if (c4 < RF4) {
            float4 p = prow[c4];
            float4 o;
            o.x = l[j].x * inv; o.y = l[j].y * inv;
            o.z = l[j].z * inv; o.w = l[j].w * inv;
            orow[c4] = o;
            float v0 = o.x * p.x, v1 = o.y * p.y, v2 = o.z * p.z, v3 = o.w * p.w;
            if (v0 > bv) { bv = v0; bi = 4 * c4; }
            if (v1 > bv) { bv = v1; bi = 4 * c4 + 1; }
            if (v2 > bv) { bv = v2; bi = 4 * c4 + 2; }
            if (v3 > bv) { bv = v3; bi = 4 * c4 + 3; }
        }
    }
#pragma unroll
    for (int o = 16; o; o >>= 1) {
        float ov = __shfl_xor_sync(0xffffffffu, bv, o);
        int   oi = __shfl_xor_sync(0xffffffffu, bi, o);
        if (ov > bv || (ov == bv && oi < bi)) { bv = ov; bi = oi; }
    }
    if (lane == 0) {
        labels[row] = bi;
        const int ptr = load_ptr_val(ptr_in);
        const int ptrc = clamp_ptr(ptr);
        float lab = (float)bi;
        cont_labels[row] = lab;
        cont_labels[BB + row] = lab;
        new_qp[ptrc + row] = lab;
        if (row == 0) new_ptr_out[0] = (float)((ptr + BB) % QQ);
    }
}

// ---------------------------------------------------------------------------
// Kernel 1: head — role-split: even blocks gemm, odd blocks classfy.
// ---------------------------------------------------------------------------
__global__ __launch_bounds__(256) void head_kernel(
    const float* __restrict__ q, const float* __restrict__ protos,
    float* __restrict__ escratch, float* __restrict__ psum,
    const float4* __restrict__ logits4, const float4* __restrict__ plabel4,
    const void* __restrict__ ptr_in,
    float4* __restrict__ out_classfy4, int* __restrict__ labels,
    float* __restrict__ cont_labels, float* __restrict__ new_qp,
    float* __restrict__ new_ptr_out)
{
    extern __shared__ uint32_t smem[];
    const int bid = blockIdx.x;
    if ((bid & 1) == 0) {
        gemm_role(bid >> 1, smem, q, protos, escratch, psum);
    } else {
        classfy_role(bid >> 1, logits4, plabel4, ptr_in,
                     out_classfy4, labels, cont_labels, new_qp, new_ptr_out);
    }
}

// ---------------------------------------------------------------------------
// Kernel 2: megatail — role-split single launch:
//   blocks [0, 2048):        bulk dup + k scatter (4 float4 per thread)
//   blocks [2048, 6144):     cluster softmax normalize (one row each)
//   blocks [6144, 7144):     prototype EMA + l2norm (one class each)
// ---------------------------------------------------------------------------
#define NQ4     (QQ * DD / 4)      // 2,097,152
#define QUART4  (NQ4 / 4)          // 524,288
#define NB4     (BB * DD / 4)      // 131,072
#define MT_BULK  (QUART4 / 256)    // 2048
#define MT_NORM  BB                // 4096
#define MT_PROTO CC                // 1000
#define MT_GRID  (MT_BULK + MT_NORM + MT_PROTO)

__global__ __launch_bounds__(256) void megatail_kernel(
    const float4* __restrict__ q4, const float4* __restrict__ k4,
    const float4* __restrict__ queue4, const float* __restrict__ qp,
    const void* __restrict__ ptr_in,
    const float4* __restrict__ escratch4, const float* __restrict__ psum,
    const float* __restrict__ qf, const float* __restrict__ protos,
    const int* __restrict__ labels,
    float4* __restrict__ contf4, float4* __restrict__ outq4,
    float* __restrict__ outqp, float* __restrict__ contl,
    float4* __restrict__ cluster4, float* __restrict__ out_proto)
{
    const int bid = blockIdx.x;
    const int tid = threadIdx.x;

    if (bid < MT_BULK) {
        // ---------------- bulk dup role (4 float4 per thread) ----------------
        const int ptrc = clamp_ptr(load_ptr_val(ptr_in));
        const int i = bid * 256 + tid;
        float4 v[4];
#pragma unroll
        for (int h = 0; h < 4; h++) v[h] = __ldcs(&queue4[i + h * QUART4]);
#pragma unroll
        for (int h = 0; h < 4; h++) __stcs(&contf4[2 * NB4 + i + h * QUART4], v[h]);
#pragma unroll
        for (int h = 0; h < 4; h++) {
            int idx = i + h * QUART4;
            int row = idx >> 5;                       // 32 float4 per row
            float4 o = v[h];
            if (row >= ptrc && row < ptrc + BB)
                o = __ldcs(&k4[(row - ptrc) * 32 + (idx & 31)]);
            __stcs(&outq4[idx], o);                   // new_queue
        }
        if (i < NB4) {
            float4 vq = __ldcs(&q4[i]);
            float4 vk = __ldcs(&k4[i]);
            __stcs(&contf4[i], vq);
            __stcs(&contf4[NB4 + i], vk);
        }
        if (i < QQ) {
            float v0 = __ldcs(&qp[i]);
            __stcs(&contl[2 * BB + i], v0);           // cont_labels tail
            if (i < ptrc || i >= ptrc + BB)
                __stcs(&outqp[i], v0);                // new_queue_pseudo
        }
    } else if (bid < MT_BULK + MT_NORM) {
        // ---------------- cluster softmax normalize role ----------------
        const int r = bid - MT_BULK;
        const int RF4 = CC / 4;                       // 250
        float total = 0.f;
#pragma unroll
        for (int j = 0; j < 8; j++) total += psum[(size_t)r * 8 + j];
        const float inv = 1.0f / total;
        if (tid < RF4) {
            float4 e = escratch4[(size_t)r * RF4 + tid];
            e.x *= inv; e.y *= inv; e.z *= inv; e.w *= inv;
            cluster4[(size_t)r * RF4 + tid] = e;
        }
    } else {
        // ---------------- prototype EMA role ----------------
        const int c = bid - MT_BULK - MT_NORM;
        __shared__ int sc[256];
        __shared__ int idxbuf[BB];
        __shared__ float ws[4];

        const int base = tid * 16;
        int cnt = 0;
#pragma unroll 8
        for (int j = 0; j < 16; j++) if (__ldg(&labels[base + j]) == c) cnt++;
        sc[tid] = cnt;
        __syncthreads();
#pragma unroll
        for (int d = 1; d < 256; d <<= 1) {
            int v = (tid >= d) ? sc[tid - d] : 0;
            __syncthreads();
            sc[tid] += v;
            __syncthreads();
        }
        const int total = sc[255];
        int w = sc[tid] - cnt;
#pragma unroll 8
        for (int j = 0; j < 16; j++) {
            int i = base + j;
            if (__ldg(&labels[i]) == c) idxbuf[w++] = i;
        }
        __syncthreads();

        float acc = 0.f;
        if (tid < DD) {
            acc = protos[(size_t)c * DD + tid];
            for (int j = 0; j < total; j++)
                acc = PROTO_M * acc + (1.0f - PROTO_M) * qf[(size_t)idxbuf[j] * DD + tid];
        }
        float s = acc * acc;
#pragma unroll
        for (int o = 16; o; o >>= 1) s += __shfl_xor_sync(0xffffffffu, s, o);
        if (tid < DD && (tid & 31) == 0) ws[tid >> 5] = s;
        __syncthreads();
        if (tid < DD) {
            float tot = ws[0] + ws[1] + ws[2] + ws[3];
            float inv = 1.0f / fmaxf(sqrtf(tot), 1e-12f);
            out_proto[(size_t)c * DD + tid] = acc * inv;
        }
    }
}

// ---------------------------------------------------------------------------
static bool g_init = false;

extern "C" void kernel_launch(void* const* d_in, const int* in_sizes, int n_in,
                              void* d_out, int out_size)
{
    const float* q       = (const float*)d_in[0];
    const float* k       = (const float*)d_in[1];
    const float* logits  = (const float*)d_in[2];
    const float* plabel  = (const float*)d_in[3];
    const float* protos  = (const float*)d_in[4];
    const float* queue   = (const float*)d_in[5];
    const float* queuep  = (const float*)d_in[6];
    const void*  ptr_in  = d_in[7];

    float* out = (float*)d_out;
    float* out_classfy = out + OFF_CLASSFY;
    float* out_cluster = out + OFF_CLUSTER;
    float* out_contf   = out + OFF_CONTF;
    float* out_contl   = out + OFF_CONTL;
    float* out_proto   = out + OFF_PROTO;
    float* out_queue   = out + OFF_QUEUE;
    float* out_qp      = out + OFF_QP;
    float* out_ptr     = out + OFF_PTR;

    float* escratch;
    cudaGetSymbolAddress((void**)&escratch, g_logits);
    float* psum;
    cudaGetSymbolAddress((void**)&psum, g_psum);
    int* labels;
    cudaGetSymbolAddress((void**)&labels, g_labels);

    if (!g_init) {
        cudaFuncSetAttribute(head_kernel,
                             cudaFuncAttributeMaxDynamicSharedMemorySize,
                             GEMM_SMEM_BYTES);
        g_init = true;
    }

    cudaStream_t s = 0;

    // 1) head: gemm (even blocks) + classfy (odd blocks)
    head_kernel<<<GEMM_BLOCKS + CLS_BLOCKS, 256, GEMM_SMEM_BYTES, s>>>(
        q, protos, escratch, psum,
        (const float4*)logits, (const float4*)plabel, ptr_in,
        (float4*)out_classfy, labels, out_contl, out_qp, out_ptr);

    // 2) megatail: bulkdup + cluster normalize + proto EMA (one launch)
    megatail_kernel<<<MT_GRID, 256, 0, s>>>(
        (const float4*)q, (const float4*)k, (const float4*)queue, queuep,
        ptr_in, (const float4*)escratch, psum, q, protos, labels,
        (float4*)out_contf, (float4*)out_queue, out_qp, out_contl,
        (float4*)out_cluster, out_proto);
}

// round 7
// speedup vs baseline: 1.9208x; 1.3889x over previous
#include <cuda_runtime.h>
#include <cuda_bf16.h>
#include <math.h>
#include <stdint.h>

// Problem constants
#define BB 4096     // batch
#define CC 1000     // classes
#define DD 128      // feature dim
#define QQ 65536    // queue length
#define PROTO_M 0.99f

// ---- output layout (flat float32 concat, reference return order) ----
static const size_t OFF_CLASSFY = 0;
static const size_t OFF_CLUSTER = (size_t)BB * CC;
static const size_t OFF_CONTF   = OFF_CLUSTER + (size_t)BB * CC;
static const size_t OFF_CONTL   = OFF_CONTF + (size_t)(2 * BB + QQ) * DD;
static const size_t OFF_PROTO   = OFF_CONTL + (size_t)(2 * BB + QQ);
static const size_t OFF_QUEUE   = OFF_PROTO + (size_t)CC * DD;
static const size_t OFF_QP      = OFF_QUEUE + (size_t)QQ * DD;
static const size_t OFF_PTR     = OFF_QP + (size_t)QQ;

// scratch (no allocations allowed -> device globals)
__device__ float g_logits[(size_t)BB * CC];  // exp(logit) after head
__device__ float g_psum[(size_t)BB * 8];     // per-(row, n-block) exp partial sums
__device__ int   g_labels[BB];

// ---------------------------------------------------------------------------
__device__ __forceinline__ int load_ptr_val(const void* p)
{
    int iv = *(const int*)p;
    if (iv >= 0 && iv <= QQ) return iv;       // stored as int32
    float fv = *(const float*)p;              // stored as float32
    return (int)fv;
}
__device__ __forceinline__ int clamp_ptr(int ptr)
{
    int ptrc = ptr;
    if (ptrc < 0) ptrc = 0;
    if (ptrc > QQ - BB) ptrc = QQ - BB;
    return ptrc;
}

// ---------------------------------------------------------------------------
// tf32 helpers
// ---------------------------------------------------------------------------
__device__ __forceinline__ uint32_t f32_to_tf32(float f)
{
    uint32_t r;
    asm volatile("cvt.rna.tf32.f32 %0, %1;" : "=r"(r) : "f"(f));
    return r;
}

__device__ __forceinline__ void mma_tf32(float c[4],
    uint32_t a0, uint32_t a1, uint32_t a2, uint32_t a3,
    uint32_t b0, uint32_t b1)
{
    asm volatile(
        "mma.sync.aligned.m16n8k8.row.col.f32.tf32.tf32.f32 "
        "{%0,%1,%2,%3}, {%4,%5,%6,%7}, {%8,%9}, {%0,%1,%2,%3};"
        : "+f"(c[0]), "+f"(c[1]), "+f"(c[2]), "+f"(c[3])
        : "r"(a0), "r"(a1), "r"(a2), "r"(a3), "r"(b0), "r"(b1));
}

#define TBM 64
#define TBN 128
#define TBK 64
#define LDPK (TBK + 4)   // 68 words per smem row
#define GEMM_SMEM_BYTES ((TBM + TBN) * LDPK * 4)   // 52,224 bytes -> 4 blk/SM
#define GEMM_BLOCKS ((CC + TBN - 1) / TBN * (BB / TBM))   // 8 * 64 = 512
#define CLS_BLOCKS  (BB / 8)                               // 512

// ---------------------------------------------------------------------------
// gemm role: exp(q @ protos^T) + per-(row, n-block) partial sums.
// TBK=64, two k-slices (52 KB smem).
// ---------------------------------------------------------------------------
__device__ void gemm_role(int gb, uint32_t* smem,
    const float* __restrict__ Aq, const float* __restrict__ Bp,
    float* __restrict__ Eout, float* __restrict__ psum)
{
    uint32_t* As = smem;                  // [TBM][LDPK]
    uint32_t* Bs = smem + TBM * LDPK;     // [TBN][LDPK]
    __shared__ float smem_part[TBM][4];

    const int tid  = threadIdx.x;
    const int lane = tid & 31;
    const int w    = tid >> 5;
    const int wm   = w & 1;
    const int wn   = w >> 1;
    const int g    = lane >> 2;
    const int tig  = lane & 3;
    const int bx   = gb & 7;              // 8 n-blocks
    const int by   = gb >> 3;             // 64 m-blocks
    const int m0   = by * TBM;
    const int n0   = bx * TBN;
    const int rbase = wm * 32;
    const int cbase = wn * 32;

    float c[2][4][4];
#pragma unroll
    for (int mt = 0; mt < 2; mt++)
#pragma unroll
        for (int nt = 0; nt < 4; nt++)
#pragma unroll
            for (int i = 0; i < 4; i++) c[mt][nt][i] = 0.f;

#pragma unroll
    for (int kt = 0; kt < 2; kt++) {
        const int kk = kt * TBK;
        if (kt > 0) __syncthreads();      // previous slice fully consumed
        // load A(64x64) + B(128x64): (64+128)*8 = 1536 slots of 8 cols
#pragma unroll
        for (int it = 0; it < 6; it++) {
            int slot = it * 256 + tid;
            float4 lo, hi;
            uint32_t* dst;
            if (slot < TBM * 8) {
                int r = slot >> 3, gp = slot & 7;
                const float* src = Aq + (size_t)(m0 + r) * DD + kk + gp * 8;
                lo = *(const float4*)src;
                hi = *(const float4*)(src + 4);
                dst = As + r * LDPK + gp * 8;
            } else {
                int s = slot - TBM * 8;
                int r = s >> 3, gp = s & 7;
                int n = n0 + r;
                if (n < CC) {
                    const float* src = Bp + (size_t)n * DD + kk + gp * 8;
                    lo = *(const float4*)src;
                    hi = *(const float4*)(src + 4);
                } else {
                    lo = make_float4(0.f, 0.f, 0.f, 0.f);
                    hi = lo;
                }
                dst = Bs + r * LDPK + gp * 8;
            }
            // interleave pairs (c, c+4) -> (2c, 2c+1) within the 8-col group
            uint4 o0, o1;
            o0.x = f32_to_tf32(lo.x); o0.y = f32_to_tf32(hi.x);
            o0.z = f32_to_tf32(lo.y); o0.w = f32_to_tf32(hi.y);
            o1.x = f32_to_tf32(lo.z); o1.y = f32_to_tf32(hi.z);
            o1.z = f32_to_tf32(lo.w); o1.w = f32_to_tf32(hi.w);
            *(uint4*)dst = o0;
            *(uint4*)(dst + 4) = o1;
        }
        __syncthreads();

#pragma unroll
        for (int ks = 0; ks < TBK / 8; ks++) {
            const int k0 = ks * 8;
            uint2 afr[2][2];
#pragma unroll
            for (int mt = 0; mt < 2; mt++) {
                int rb = rbase + mt * 16 + g;
                afr[mt][0] = *(const uint2*)(As + rb * LDPK + k0 + 2 * tig);
                afr[mt][1] = *(const uint2*)(As + (rb + 8) * LDPK + k0 + 2 * tig);
            }
            uint2 bfr[4];
#pragma unroll
            for (int nt = 0; nt < 4; nt++) {
                int cb = cbase + nt * 8 + g;
                bfr[nt] = *(const uint2*)(Bs + cb * LDPK + k0 + 2 * tig);
            }
#pragma unroll
            for (int mt = 0; mt < 2; mt++)
#pragma unroll
                for (int nt = 0; nt < 4; nt++)
                    mma_tf32(c[mt][nt],
                             afr[mt][0].x, afr[mt][1].x, afr[mt][0].y, afr[mt][1].y,
                             bfr[nt].x, bfr[nt].y);
        }
    }

    // ---- epilogue: exp, store, per-row partial sums (deterministic) ----
    float rs[2][2] = {{0.f, 0.f}, {0.f, 0.f}};
#pragma unroll
    for (int mt = 0; mt < 2; mt++) {
#pragma unroll
        for (int nt = 0; nt < 4; nt++) {
            int m = m0 + rbase + mt * 16 + g;
            int n = n0 + cbase + nt * 8 + 2 * tig;
            if (n < CC) {
                float e0 = __expf(c[mt][nt][0]);
                float e1 = __expf(c[mt][nt][1]);
                float e2 = __expf(c[mt][nt][2]);
                float e3 = __expf(c[mt][nt][3]);
                *(float2*)(Eout + (size_t)m * CC + n) = make_float2(e0, e1);
                *(float2*)(Eout + (size_t)(m + 8) * CC + n) = make_float2(e2, e3);
                rs[mt][0] += e0 + e1;
                rs[mt][1] += e2 + e3;
            }
        }
    }
#pragma unroll
    for (int o = 1; o <= 2; o <<= 1) {
#pragma unroll
        for (int mt = 0; mt < 2; mt++) {
            rs[mt][0] += __shfl_xor_sync(0xffffffffu, rs[mt][0], o);
            rs[mt][1] += __shfl_xor_sync(0xffffffffu, rs[mt][1], o);
        }
    }
    if (tig == 0) {
#pragma unroll
        for (int mt = 0; mt < 2; mt++) {
            smem_part[rbase + mt * 16 + g][wn]     = rs[mt][0];
            smem_part[rbase + mt * 16 + 8 + g][wn] = rs[mt][1];
        }
    }
    __syncthreads();
    if (tid < TBM) {
        float s = smem_part[tid][0] + smem_part[tid][1]
                + smem_part[tid][2] + smem_part[tid][3];
        psum[(size_t)(m0 + tid) * 8 + bx] = s;
    }
}

// ---------------------------------------------------------------------------
// classfy role: warp-per-row softmax + argmax(softmax*plabel) + labels epi.
// ---------------------------------------------------------------------------
__device__ void classfy_role(int cb,
    const float4* __restrict__ logits4, const float4* __restrict__ plabel4,
    const void* __restrict__ ptr_in,
    float4* __restrict__ out4, int* __restrict__ labels,
    float* __restrict__ cont_labels, float* __restrict__ new_qp,
    float* __restrict__ new_ptr_out)
{
    const int tid  = threadIdx.x;
    const int w    = tid >> 5;
    const int lane = tid & 31;
    const int row  = cb * 8 + w;
    const int RF4  = CC / 4;               // 250
    const float4* lrow = logits4 + (size_t)row * RF4;
    const float4* prow = plabel4 + (size_t)row * RF4;
    float4* orow = out4 + (size_t)row * RF4;

    float4 l[8];
    float mx = -1e30f;
#pragma unroll
    for (int j = 0; j < 8; j++) {
        int c4 = j * 32 + lane;
        if (c4 < RF4) {
            l[j] = lrow[c4];
            mx = fmaxf(mx, fmaxf(fmaxf(l[j].x, l[j].y), fmaxf(l[j].z, l[j].w)));
        } else {
            l[j] = make_float4(-1e30f, -1e30f, -1e30f, -1e30f);
        }
    }
#pragma unroll
    for (int o = 16; o; o >>= 1) mx = fmaxf(mx, __shfl_xor_sync(0xffffffffu, mx, o));

    float sum = 0.f;
#pragma unroll
    for (int j = 0; j < 8; j++) {
        l[j].x = __expf(l[j].x - mx);
        l[j].y = __expf(l[j].y - mx);
        l[j].z = __expf(l[j].z - mx);
        l[j].w = __expf(l[j].w - mx);
        sum += l[j].x + l[j].y + l[j].z + l[j].w;
    }
#pragma unroll
    for (int o = 16; o; o >>= 1) sum += __shfl_xor_sync(0xffffffffu, sum, o);
    const float inv = 1.0f / sum;

    float bv = -1.0f;
    int bi = 0x7fffffff;
#pragma unroll
    for (int j = 0; j < 8; j++) {
        int c4 = j * 32 + lane;
        if (c4 < RF4) {
            float4 p = prow[c4];
            float4 o;
            o.x = l[j].x * inv; o.y = l[j].y * inv;
            o.z = l[j].z * inv; o.w = l[j].w * inv;
            orow[c4] = o;
            float v0 = o.x * p.x, v1 = o.y * p.y, v2 = o.z * p.z, v3 = o.w * p.w;
            if (v0 > bv) { bv = v0; bi = 4 * c4; }
            if (v1 > bv) { bv = v1; bi = 4 * c4 + 1; }
            if (v2 > bv) { bv = v2; bi = 4 * c4 + 2; }
            if (v3 > bv) { bv = v3; bi = 4 * c4 + 3; }
        }
    }
#pragma unroll
    for (int o = 16; o; o >>= 1) {
        float ov = __shfl_xor_sync(0xffffffffu, bv, o);
        int   oi = __shfl_xor_sync(0xffffffffu, bi, o);
        if (ov > bv || (ov == bv && oi < bi)) { bv = ov; bi = oi; }
    }
    if (lane == 0) {
        labels[row] = bi;
        const int ptr = load_ptr_val(ptr_in);
        const int ptrc = clamp_ptr(ptr);
        float lab = (float)bi;
        cont_labels[row] = lab;
        cont_labels[BB + row] = lab;
        new_qp[ptrc + row] = lab;
        if (row == 0) new_ptr_out[0] = (float)((ptr + BB) % QQ);
    }
}

// ---------------------------------------------------------------------------
// Kernel 1: head — even blocks gemm, odd blocks classfy (4 blk/SM now).
// ---------------------------------------------------------------------------
__global__ __launch_bounds__(256) void head_kernel(
    const float* __restrict__ q, const float* __restrict__ protos,
    float* __restrict__ escratch, float* __restrict__ psum,
    const float4* __restrict__ logits4, const float4* __restrict__ plabel4,
    const void* __restrict__ ptr_in,
    float4* __restrict__ out_classfy4, int* __restrict__ labels,
    float* __restrict__ cont_labels, float* __restrict__ new_qp,
    float* __restrict__ new_ptr_out)
{
    extern __shared__ uint32_t smem[];
    const int bid = blockIdx.x;
    if ((bid & 1) == 0) {
        gemm_role(bid >> 1, smem, q, protos, escratch, psum);
    } else {
        classfy_role(bid >> 1, logits4, plabel4, ptr_in,
                     out_classfy4, labels, cont_labels, new_qp, new_ptr_out);
    }
}

// ---------------------------------------------------------------------------
// Kernel 2: megatail — roles INTERLEAVED per 7-block group [4 bulk,1 norm,2 proto]
//   bulk:  2048 blocks, 4 float4/thread queue dup + k scatter
//   norm:  512 blocks, warp-per-row (8 rows/block) softmax normalize
//   proto: 1024 blocks (>=1000 skip), EMA + l2norm, int4 label loads
// ---------------------------------------------------------------------------
#define NQ4     (QQ * DD / 4)      // 2,097,152
#define QUART4  (NQ4 / 4)          // 524,288
#define NB4     (BB * DD / 4)      // 131,072
#define MT_GROUPS 512
#define MT_GRID  (MT_GROUPS * 7)   // 3584

__global__ __launch_bounds__(256) void megatail_kernel(
    const float4* __restrict__ q4, const float4* __restrict__ k4,
    const float4* __restrict__ queue4, const float* __restrict__ qp,
    const void* __restrict__ ptr_in,
    const float4* __restrict__ escratch4, const float* __restrict__ psum,
    const float* __restrict__ qf, const float* __restrict__ protos,
    const int* __restrict__ labels,
    float4* __restrict__ contf4, float4* __restrict__ outq4,
    float* __restrict__ outqp, float* __restrict__ contl,
    float4* __restrict__ cluster4, float* __restrict__ out_proto)
{
    const int grp = blockIdx.x / 7;
    const int r   = blockIdx.x % 7;
    const int tid = threadIdx.x;

    if (r < 4) {
        // ---------------- bulk dup role ----------------
        const int bb = grp * 4 + r;                    // 0..2047
        const int ptrc = clamp_ptr(load_ptr_val(ptr_in));
        const int i = bb * 256 + tid;
        float4 v[4];
#pragma unroll
        for (int h = 0; h < 4; h++) v[h] = __ldcs(&queue4[i + h * QUART4]);
#pragma unroll
        for (int h = 0; h < 4; h++) __stcs(&contf4[2 * NB4 + i + h * QUART4], v[h]);
#pragma unroll
        for (int h = 0; h < 4; h++) {
            int idx = i + h * QUART4;
            int row = idx >> 5;                        // 32 float4 per row
            float4 o = v[h];
            if (row >= ptrc && row < ptrc + BB)
                o = __ldcs(&k4[(row - ptrc) * 32 + (idx & 31)]);
            __stcs(&outq4[idx], o);                    // new_queue
        }
        if (i < NB4) {
            float4 vq = __ldcs(&q4[i]);
            float4 vk = __ldcs(&k4[i]);
            __stcs(&contf4[i], vq);
            __stcs(&contf4[NB4 + i], vk);
        }
        if (i < QQ) {
            float v0 = __ldcs(&qp[i]);
            __stcs(&contl[2 * BB + i], v0);            // cont_labels tail
            if (i < ptrc || i >= ptrc + BB)
                __stcs(&outqp[i], v0);                 // new_queue_pseudo
        }
    } else if (r == 4) {
        // ---------------- normalize role: warp-per-row, 8 rows ----------------
        const int w    = tid >> 5;
        const int lane = tid & 31;
        const int row  = grp * 8 + w;                  // 0..4095
        const int RF4  = CC / 4;                       // 250
        float total = 0.f;
#pragma unroll
        for (int j = 0; j < 8; j++) total += psum[(size_t)row * 8 + j];
        const float inv = 1.0f / total;
        const float4* src = escratch4 + (size_t)row * RF4;
        float4* dst = cluster4 + (size_t)row * RF4;
#pragma unroll
        for (int j = 0; j < 8; j++) {
            int c4 = j * 32 + lane;
            if (c4 < RF4) {
                float4 e = src[c4];
                e.x *= inv; e.y *= inv; e.z *= inv; e.w *= inv;
                dst[c4] = e;
            }
        }
    } else {
        // ---------------- prototype EMA role ----------------
        const int c = grp * 2 + (r - 5);               // 0..1023
        if (c >= CC) return;
        __shared__ int sc[256];
        __shared__ int idxbuf[BB];
        __shared__ float ws[4];

        const int4* lab4 = (const int4*)labels;
        int4 lv[4];
#pragma unroll
        for (int j = 0; j < 4; j++) lv[j] = __ldg(&lab4[tid * 4 + j]);
        int cnt = 0;
#pragma unroll
        for (int j = 0; j < 4; j++) {
            cnt += (lv[j].x == c) + (lv[j].y == c) + (lv[j].z == c) + (lv[j].w == c);
        }
        sc[tid] = cnt;
        __syncthreads();
#pragma unroll
        for (int d = 1; d < 256; d <<= 1) {
            int v = (tid >= d) ? sc[tid - d] : 0;
            __syncthreads();
            sc[tid] += v;
            __syncthreads();
        }
        const int total = sc[255];
        int wofs = sc[tid] - cnt;
        const int base = tid * 16;
#pragma unroll
        for (int j = 0; j < 4; j++) {
            if (lv[j].x == c) idxbuf[wofs++] = base + 4 * j;
            if (lv[j].y == c) idxbuf[wofs++] = base + 4 * j + 1;
            if (lv[j].z == c) idxbuf[wofs++] = base + 4 * j + 2;
            if (lv[j].w == c) idxbuf[wofs++] = base + 4 * j + 3;
        }
        __syncthreads();

        float acc = 0.f;
        if (tid < DD) {
            acc = protos[(size_t)c * DD + tid];
            for (int j = 0; j < total; j++)
                acc = PROTO_M * acc + (1.0f - PROTO_M) * qf[(size_t)idxbuf[j] * DD + tid];
        }
        float s = acc * acc;
#pragma unroll
        for (int o = 16; o; o >>= 1) s += __shfl_xor_sync(0xffffffffu, s, o);
        if (tid < DD && (tid & 31) == 0) ws[tid >> 5] = s;
        __syncthreads();
        if (tid < DD) {
            float tot = ws[0] + ws[1] + ws[2] + ws[3];
            float inv = 1.0f / fmaxf(sqrtf(tot), 1e-12f);
            out_proto[(size_t)c * DD + tid] = acc * inv;
        }
    }
}

// ---------------------------------------------------------------------------
static bool g_init = false;

extern "C" void kernel_launch(void* const* d_in, const int* in_sizes, int n_in,
                              void* d_out, int out_size)
{
    const float* q       = (const float*)d_in[0];
    const float* k       = (const float*)d_in[1];
    const float* logits  = (const float*)d_in[2];
    const float* plabel  = (const float*)d_in[3];
    const float* protos  = (const float*)d_in[4];
    const float* queue   = (const float*)d_in[5];
    const float* queuep  = (const float*)d_in[6];
    const void*  ptr_in  = d_in[7];

    float* out = (float*)d_out;
    float* out_classfy = out + OFF_CLASSFY;
    float* out_cluster = out + OFF_CLUSTER;
    float* out_contf   = out + OFF_CONTF;
    float* out_contl   = out + OFF_CONTL;
    float* out_proto   = out + OFF_PROTO;
    float* out_queue   = out + OFF_QUEUE;
    float* out_qp      = out + OFF_QP;
    float* out_ptr     = out + OFF_PTR;

    float* escratch;
    cudaGetSymbolAddress((void**)&escratch, g_logits);
    float* psum;
    cudaGetSymbolAddress((void**)&psum, g_psum);
    int* labels;
    cudaGetSymbolAddress((void**)&labels, g_labels);

    if (!g_init) {
        cudaFuncSetAttribute(head_kernel,
                             cudaFuncAttributeMaxDynamicSharedMemorySize,
                             GEMM_SMEM_BYTES);
        g_init = true;
    }

    cudaStream_t s = 0;

    // 1) head: gemm (even blocks) + classfy (odd blocks)
    head_kernel<<<GEMM_BLOCKS + CLS_BLOCKS, 256, GEMM_SMEM_BYTES, s>>>(
        q, protos, escratch, psum,
        (const float4*)logits, (const float4*)plabel, ptr_in,
        (float4*)out_classfy, labels, out_contl, out_qp, out_ptr);

    // 2) megatail: interleaved bulkdup + normalize + proto EMA
    megatail_kernel<<<MT_GRID, 256, 0, s>>>(
        (const float4*)q, (const float4*)k, (const float4*)queue, queuep,
        ptr_in, (const float4*)escratch, psum, q, protos, labels,
        (float4*)out_contf, (float4*)out_queue, out_qp, out_contl,
        (float4*)out_cluster, out_proto);
}

// round 8
// speedup vs baseline: 1.9670x; 1.0240x over previous
#include <cuda_runtime.h>
#include <cuda_bf16.h>
#include <math.h>
#include <stdint.h>

// Problem constants
#define BB 4096     // batch
#define CC 1000     // classes
#define DD 128      // feature dim
#define QQ 65536    // queue length
#define PROTO_M 0.99f

// ---- output layout (flat float32 concat, reference return order) ----
static const size_t OFF_CLASSFY = 0;
static const size_t OFF_CLUSTER = (size_t)BB * CC;
static const size_t OFF_CONTF   = OFF_CLUSTER + (size_t)BB * CC;
static const size_t OFF_CONTL   = OFF_CONTF + (size_t)(2 * BB + QQ) * DD;
static const size_t OFF_PROTO   = OFF_CONTL + (size_t)(2 * BB + QQ);
static const size_t OFF_QUEUE   = OFF_PROTO + (size_t)CC * DD;
static const size_t OFF_QP      = OFF_QUEUE + (size_t)QQ * DD;
static const size_t OFF_PTR     = OFF_QP + (size_t)QQ;

// scratch (no allocations allowed -> device globals)
__device__ float g_logits[(size_t)BB * CC];  // exp(logit) after head
__device__ float g_psum[(size_t)BB * 8];     // per-(row, n-block) exp partial sums
__device__ int   g_labels[BB];

// ---------------------------------------------------------------------------
__device__ __forceinline__ int load_ptr_val(const void* p)
{
    int iv = *(const int*)p;
    if (iv >= 0 && iv <= QQ) return iv;       // stored as int32
    float fv = *(const float*)p;              // stored as float32
    return (int)fv;
}
__device__ __forceinline__ int clamp_ptr(int ptr)
{
    int ptrc = ptr;
    if (ptrc < 0) ptrc = 0;
    if (ptrc > QQ - BB) ptrc = QQ - BB;
    return ptrc;
}

// ---------------------------------------------------------------------------
// tf32 helpers
// ---------------------------------------------------------------------------
__device__ __forceinline__ uint32_t f32_to_tf32(float f)
{
    uint32_t r;
    asm volatile("cvt.rna.tf32.f32 %0, %1;" : "=r"(r) : "f"(f));
    return r;
}

__device__ __forceinline__ void mma_tf32(float c[4],
    uint32_t a0, uint32_t a1, uint32_t a2, uint32_t a3,
    uint32_t b0, uint32_t b1)
{
    asm volatile(
        "mma.sync.aligned.m16n8k8.row.col.f32.tf32.tf32.f32 "
        "{%0,%1,%2,%3}, {%4,%5,%6,%7}, {%8,%9}, {%0,%1,%2,%3};"
        : "+f"(c[0]), "+f"(c[1]), "+f"(c[2]), "+f"(c[3])
        : "r"(a0), "r"(a1), "r"(a2), "r"(a3), "r"(b0), "r"(b1));
}

#define TBM 64
#define TBN 128
#define TBK 64
#define LDPK (TBK + 4)   // 68 words per smem row
#define GEMM_SMEM_BYTES ((TBM + TBN) * LDPK * 4)   // 52,224 bytes -> 4 blk/SM

// ---------------------------------------------------------------------------
// gemm role: exp(q @ protos^T) + per-(row, n-block) partial sums.
// ---------------------------------------------------------------------------
__device__ void gemm_role(int gb, uint32_t* smem,
    const float* __restrict__ Aq, const float* __restrict__ Bp,
    float* __restrict__ Eout, float* __restrict__ psum)
{
    uint32_t* As = smem;                  // [TBM][LDPK]
    uint32_t* Bs = smem + TBM * LDPK;     // [TBN][LDPK]
    __shared__ float smem_part[TBM][4];

    const int tid  = threadIdx.x;
    const int lane = tid & 31;
    const int w    = tid >> 5;
    const int wm   = w & 1;
    const int wn   = w >> 1;
    const int g    = lane >> 2;
    const int tig  = lane & 3;
    const int bx   = gb & 7;              // 8 n-blocks
    const int by   = gb >> 3;             // 64 m-blocks
    const int m0   = by * TBM;
    const int n0   = bx * TBN;
    const int rbase = wm * 32;
    const int cbase = wn * 32;

    float c[2][4][4];
#pragma unroll
    for (int mt = 0; mt < 2; mt++)
#pragma unroll
        for (int nt = 0; nt < 4; nt++)
#pragma unroll
            for (int i = 0; i < 4; i++) c[mt][nt][i] = 0.f;

#pragma unroll
    for (int kt = 0; kt < 2; kt++) {
        const int kk = kt * TBK;
        if (kt > 0) __syncthreads();
#pragma unroll
        for (int it = 0; it < 6; it++) {
            int slot = it * 256 + tid;
            float4 lo, hi;
            uint32_t* dst;
            if (slot < TBM * 8) {
                int r = slot >> 3, gp = slot & 7;
                const float* src = Aq + (size_t)(m0 + r) * DD + kk + gp * 8;
                lo = *(const float4*)src;
                hi = *(const float4*)(src + 4);
                dst = As + r * LDPK + gp * 8;
            } else {
                int s = slot - TBM * 8;
                int r = s >> 3, gp = s & 7;
                int n = n0 + r;
                if (n < CC) {
                    const float* src = Bp + (size_t)n * DD + kk + gp * 8;
                    lo = *(const float4*)src;
                    hi = *(const float4*)(src + 4);
                } else {
                    lo = make_float4(0.f, 0.f, 0.f, 0.f);
                    hi = lo;
                }
                dst = Bs + r * LDPK + gp * 8;
            }
            uint4 o0, o1;
            o0.x = f32_to_tf32(lo.x); o0.y = f32_to_tf32(hi.x);
            o0.z = f32_to_tf32(lo.y); o0.w = f32_to_tf32(hi.y);
            o1.x = f32_to_tf32(lo.z); o1.y = f32_to_tf32(hi.z);
            o1.z = f32_to_tf32(lo.w); o1.w = f32_to_tf32(hi.w);
            *(uint4*)dst = o0;
            *(uint4*)(dst + 4) = o1;
        }
        __syncthreads();

#pragma unroll
        for (int ks = 0; ks < TBK / 8; ks++) {
            const int k0 = ks * 8;
            uint2 afr[2][2];
#pragma unroll
            for (int mt = 0; mt < 2; mt++) {
                int rb = rbase + mt * 16 + g;
                afr[mt][0] = *(const uint2*)(As + rb * LDPK + k0 + 2 * tig);
                afr[mt][1] = *(const uint2*)(As + (rb + 8) * LDPK + k0 + 2 * tig);
            }
            uint2 bfr[4];
#pragma unroll
            for (int nt = 0; nt < 4; nt++) {
                int cb = cbase + nt * 8 + g;
                bfr[nt] = *(const uint2*)(Bs + cb * LDPK + k0 + 2 * tig);
            }
#pragma unroll
            for (int mt = 0; mt < 2; mt++)
#pragma unroll
                for (int nt = 0; nt < 4; nt++)
                    mma_tf32(c[mt][nt],
                             afr[mt][0].x, afr[mt][1].x, afr[mt][0].y, afr[mt][1].y,
                             bfr[nt].x, bfr[nt].y);
        }
    }

    // epilogue: exp, store, per-row partial sums (deterministic)
    float rs[2][2] = {{0.f, 0.f}, {0.f, 0.f}};
#pragma unroll
    for (int mt = 0; mt < 2; mt++) {
#pragma unroll
        for (int nt = 0; nt < 4; nt++) {
            int m = m0 + rbase + mt * 16 + g;
            int n = n0 + cbase + nt * 8 + 2 * tig;
            if (n < CC) {
                float e0 = __expf(c[mt][nt][0]);
                float e1 = __expf(c[mt][nt][1]);
                float e2 = __expf(c[mt][nt][2]);
                float e3 = __expf(c[mt][nt][3]);
                *(float2*)(Eout + (size_t)m * CC + n) = make_float2(e0, e1);
                *(float2*)(Eout + (size_t)(m + 8) * CC + n) = make_float2(e2, e3);
                rs[mt][0] += e0 + e1;
                rs[mt][1] += e2 + e3;
            }
        }
    }
#pragma unroll
    for (int o = 1; o <= 2; o <<= 1) {
#pragma unroll
        for (int mt = 0; mt < 2; mt++) {
            rs[mt][0] += __shfl_xor_sync(0xffffffffu, rs[mt][0], o);
            rs[mt][1] += __shfl_xor_sync(0xffffffffu, rs[mt][1], o);
        }
    }
    if (tig == 0) {
#pragma unroll
        for (int mt = 0; mt < 2; mt++) {
            smem_part[rbase + mt * 16 + g][wn]     = rs[mt][0];
            smem_part[rbase + mt * 16 + 8 + g][wn] = rs[mt][1];
        }
    }
    __syncthreads();
    if (tid < TBM) {
        float s = smem_part[tid][0] + smem_part[tid][1]
                + smem_part[tid][2] + smem_part[tid][3];
        psum[(size_t)(m0 + tid) * 8 + bx] = s;
    }
}

// ---------------------------------------------------------------------------
// classfy role: warp-per-row softmax + argmax(softmax*plabel) + labels epi.
// ---------------------------------------------------------------------------
__device__ void classfy_role(int cb,
    const float4* __restrict__ logits4, const float4* __restrict__ plabel4,
    const void* __restrict__ ptr_in,
    float4* __restrict__ out4, int* __restrict__ labels,
    float* __restrict__ cont_labels, float* __restrict__ new_qp,
    float* __restrict__ new_ptr_out)
{
    const int tid  = threadIdx.x;
    const int w    = tid >> 5;
    const int lane = tid & 31;
    const int row  = cb * 8 + w;
    const int RF4  = CC / 4;               // 250
    const float4* lrow = logits4 + (size_t)row * RF4;
    const float4* prow = plabel4 + (size_t)row * RF4;
    float4* orow = out4 + (size_t)row * RF4;

    float4 l[8];
    float mx = -1e30f;
#pragma unroll
    for (int j = 0; j < 8; j++) {
        int c4 = j * 32 + lane;
        if (c4 < RF4) {
            l[j] = lrow[c4];
            mx = fmaxf(mx, fmaxf(fmaxf(l[j].x, l[j].y), fmaxf(l[j].z, l[j].w)));
        } else {
            l[j] = make_float4(-1e30f, -1e30f, -1e30f, -1e30f);
        }
    }
#pragma unroll
    for (int o = 16; o; o >>= 1) mx = fmaxf(mx, __shfl_xor_sync(0xffffffffu, mx, o));

    float sum = 0.f;
#pragma unroll
    for (int j = 0; j < 8; j++) {
        l[j].x = __expf(l[j].x - mx);
        l[j].y = __expf(l[j].y - mx);
        l[j].z = __expf(l[j].z - mx);
        l[j].w = __expf(l[j].w - mx);
        sum += l[j].x + l[j].y + l[j].z + l[j].w;
    }
#pragma unroll
    for (int o = 16; o; o >>= 1) sum += __shfl_xor_sync(0xffffffffu, sum, o);
    const float inv = 1.0f / sum;

    float bv = -1.0f;
    int bi = 0x7fffffff;
#pragma unroll
    for (int j = 0; j < 8; j++) {
        int c4 = j * 32 + lane;
        if (c4 < RF4) {
            float4 p = prow[c4];
            float4 o;
            o.x = l[j].x * inv; o.y = l[j].y * inv;
            o.z = l[j].z * inv; o.w = l[j].w * inv;
            orow[c4] = o;
            float v0 = o.x * p.x, v1 = o.y * p.y, v2 = o.z * p.z, v3 = o.w * p.w;
            if (v0 > bv) { bv = v0; bi = 4 * c4; }
            if (v1 > bv) { bv = v1; bi = 4 * c4 + 1; }
            if (v2 > bv) { bv = v2; bi = 4 * c4 + 2; }
            if (v3 > bv) { bv = v3; bi = 4 * c4 + 3; }
        }
    }
#pragma unroll
    for (int o = 16; o; o >>= 1) {
        float ov = __shfl_xor_sync(0xffffffffu, bv, o);
        int   oi = __shfl_xor_sync(0xffffffffu, bi, o);
        if (ov > bv || (ov == bv && oi < bi)) { bv = ov; bi = oi; }
    }
    if (lane == 0) {
        labels[row] = bi;
        const int ptr = load_ptr_val(ptr_in);
        const int ptrc = clamp_ptr(ptr);
        float lab = (float)bi;
        cont_labels[row] = lab;
        cont_labels[BB + row] = lab;
        new_qp[ptrc + row] = lab;
        if (row == 0) new_ptr_out[0] = (float)((ptr + BB) % QQ);
    }
}

// ---------------------------------------------------------------------------
// bulk role: queue dup + k scatter + q/k dup + qp dup. 512 blocks,
// 16 float4/thread in 4 batches of 4 (keeps regs bounded, MLP=4 per batch).
// ---------------------------------------------------------------------------
#define NQ4     (QQ * DD / 4)      // 2,097,152
#define NB4     (BB * DD / 4)      // 131,072
#define BULK_BLOCKS 512
#define BULK_SEG (NQ4 / 16)        // 131,072

__device__ void bulk_role(int bb,
    const float4* __restrict__ q4, const float4* __restrict__ k4,
    const float4* __restrict__ queue4, const float* __restrict__ qp,
    const void* __restrict__ ptr_in,
    float4* __restrict__ contf4, float4* __restrict__ outq4,
    float* __restrict__ outqp, float* __restrict__ contl)
{
    const int tid = threadIdx.x;
    const int ptrc = clamp_ptr(load_ptr_val(ptr_in));
    const int i = bb * 256 + tid;     // 0..131071 == NB4, exact

#pragma unroll
    for (int b = 0; b < 4; b++) {
        float4 v[4];
#pragma unroll
        for (int h = 0; h < 4; h++)
            v[h] = __ldcs(&queue4[i + (b * 4 + h) * BULK_SEG]);
#pragma unroll
        for (int h = 0; h < 4; h++)
            __stcs(&contf4[2 * NB4 + i + (b * 4 + h) * BULK_SEG], v[h]);
#pragma unroll
        for (int h = 0; h < 4; h++) {
            int idx = i + (b * 4 + h) * BULK_SEG;
            int row = idx >> 5;                        // 32 float4 per row
            float4 o = v[h];
            if (row >= ptrc && row < ptrc + BB)
                o = __ldcs(&k4[(row - ptrc) * 32 + (idx & 31)]);
            __stcs(&outq4[idx], o);                    // new_queue
        }
    }
    // q/k duplication: i spans exactly [0, NB4)
    {
        float4 vq = __ldcs(&q4[i]);
        float4 vk = __ldcs(&k4[i]);
        __stcs(&contf4[i], vq);
        __stcs(&contf4[NB4 + i], vk);
    }
    if (i < QQ) {
        float v0 = __ldcs(&qp[i]);
        __stcs(&contl[2 * BB + i], v0);            // cont_labels tail
        if (i < ptrc || i >= ptrc + BB)
            __stcs(&outqp[i], v0);                 // new_queue_pseudo
    }
}

// ---------------------------------------------------------------------------
// Kernel 1: head — interleaved [gemm, classfy, bulk] x 512 groups.
// ---------------------------------------------------------------------------
#define HEAD_GRID (512 * 3)

__global__ __launch_bounds__(256) void head_kernel(
    const float* __restrict__ q, const float* __restrict__ protos,
    float* __restrict__ escratch, float* __restrict__ psum,
    const float4* __restrict__ logits4, const float4* __restrict__ plabel4,
    const void* __restrict__ ptr_in,
    float4* __restrict__ out_classfy4, int* __restrict__ labels,
    float* __restrict__ cont_labels, float* __restrict__ new_qp,
    float* __restrict__ new_ptr_out,
    const float4* __restrict__ k4, const float4* __restrict__ queue4,
    const float* __restrict__ qp,
    float4* __restrict__ contf4, float4* __restrict__ outq4,
    float* __restrict__ outqp)
{
    extern __shared__ uint32_t smem[];
    const int grp = blockIdx.x / 3;
    const int r   = blockIdx.x % 3;
    if (r == 0) {
        gemm_role(grp, smem, q, protos, escratch, psum);
    } else if (r == 1) {
        classfy_role(grp, logits4, plabel4, ptr_in,
                     out_classfy4, labels, cont_labels, new_qp, new_ptr_out);
    } else {
        bulk_role(grp, (const float4*)q, k4, queue4, qp, ptr_in,
                  contf4, outq4, outqp, cont_labels);
    }
}

// ---------------------------------------------------------------------------
// Kernel 2: tail — interleaved [norm, proto, proto] x 512 groups.
//   norm:  512 blocks, warp-per-row (8 rows) softmax normalize
//   proto: 1024 blocks (skip >= CC), EMA + l2norm, int4 label loads
// ---------------------------------------------------------------------------
#define TAIL_GRID (512 * 3)

__global__ __launch_bounds__(256) void tail_kernel(
    const float4* __restrict__ escratch4, const float* __restrict__ psum,
    const float* __restrict__ qf, const float* __restrict__ protos,
    const int* __restrict__ labels,
    float4* __restrict__ cluster4, float* __restrict__ out_proto)
{
    const int grp = blockIdx.x / 3;
    const int r   = blockIdx.x % 3;
    const int tid = threadIdx.x;

    if (r == 0) {
        // normalize role: warp-per-row, 8 rows
        const int w    = tid >> 5;
        const int lane = tid & 31;
        const int row  = grp * 8 + w;                  // 0..4095
        const int RF4  = CC / 4;                       // 250
        float total = 0.f;
#pragma unroll
        for (int j = 0; j < 8; j++) total += psum[(size_t)row * 8 + j];
        const float inv = 1.0f / total;
        const float4* src = escratch4 + (size_t)row * RF4;
        float4* dst = cluster4 + (size_t)row * RF4;
#pragma unroll
        for (int j = 0; j < 8; j++) {
            int c4 = j * 32 + lane;
            if (c4 < RF4) {
                float4 e = src[c4];
                e.x *= inv; e.y *= inv; e.z *= inv; e.w *= inv;
                dst[c4] = e;
            }
        }
    } else {
        // prototype EMA role
        const int c = grp * 2 + (r - 1);               // 0..1023
        if (c >= CC) return;
        __shared__ int sc[256];
        __shared__ int idxbuf[BB];
        __shared__ float ws[4];

        const int4* lab4 = (const int4*)labels;
        int4 lv[4];
#pragma unroll
        for (int j = 0; j < 4; j++) lv[j] = __ldg(&lab4[tid * 4 + j]);
        int cnt = 0;
#pragma unroll
        for (int j = 0; j < 4; j++) {
            cnt += (lv[j].x == c) + (lv[j].y == c) + (lv[j].z == c) + (lv[j].w == c);
        }
        sc[tid] = cnt;
        __syncthreads();
#pragma unroll
        for (int d = 1; d < 256; d <<= 1) {
            int v = (tid >= d) ? sc[tid - d] : 0;
            __syncthreads();
            sc[tid] += v;
            __syncthreads();
        }
        const int total = sc[255];
        int wofs = sc[tid] - cnt;
        const int base = tid * 16;
#pragma unroll
        for (int j = 0; j < 4; j++) {
            if (lv[j].x == c) idxbuf[wofs++] = base + 4 * j;
            if (lv[j].y == c) idxbuf[wofs++] = base + 4 * j + 1;
            if (lv[j].z == c) idxbuf[wofs++] = base + 4 * j + 2;
            if (lv[j].w == c) idxbuf[wofs++] = base + 4 * j + 3;
        }
        __syncthreads();

        float acc = 0.f;
        if (tid < DD) {
            acc = protos[(size_t)c * DD + tid];
            for (int j = 0; j < total; j++)
                acc = PROTO_M * acc + (1.0f - PROTO_M) * qf[(size_t)idxbuf[j] * DD + tid];
        }
        float s = acc * acc;
#pragma unroll
        for (int o = 16; o; o >>= 1) s += __shfl_xor_sync(0xffffffffu, s, o);
        if (tid < DD && (tid & 31) == 0) ws[tid >> 5] = s;
        __syncthreads();
        if (tid < DD) {
            float tot = ws[0] + ws[1] + ws[2] + ws[3];
            float inv = 1.0f / fmaxf(sqrtf(tot), 1e-12f);
            out_proto[(size_t)c * DD + tid] = acc * inv;
        }
    }
}

// ---------------------------------------------------------------------------
static bool g_init = false;

extern "C" void kernel_launch(void* const* d_in, const int* in_sizes, int n_in,
                              void* d_out, int out_size)
{
    const float* q       = (const float*)d_in[0];
    const float* k       = (const float*)d_in[1];
    const float* logits  = (const float*)d_in[2];
    const float* plabel  = (const float*)d_in[3];
    const float* protos  = (const float*)d_in[4];
    const float* queue   = (const float*)d_in[5];
    const float* queuep  = (const float*)d_in[6];
    const void*  ptr_in  = d_in[7];

    float* out = (float*)d_out;
    float* out_classfy = out + OFF_CLASSFY;
    float* out_cluster = out + OFF_CLUSTER;
    float* out_contf   = out + OFF_CONTF;
    float* out_contl   = out + OFF_CONTL;
    float* out_proto   = out + OFF_PROTO;
    float* out_queue   = out + OFF_QUEUE;
    float* out_qp      = out + OFF_QP;
    float* out_ptr     = out + OFF_PTR;

    float* escratch;
    cudaGetSymbolAddress((void**)&escratch, g_logits);
    float* psum;
    cudaGetSymbolAddress((void**)&psum, g_psum);
    int* labels;
    cudaGetSymbolAddress((void**)&labels, g_labels);

    if (!g_init) {
        cudaFuncSetAttribute(head_kernel,
                             cudaFuncAttributeMaxDynamicSharedMemorySize,
                             GEMM_SMEM_BYTES);
        g_init = true;
    }

    cudaStream_t s = 0;

    // 1) head: gemm + classfy + bulk, interleaved roles
    head_kernel<<<HEAD_GRID, 256, GEMM_SMEM_BYTES, s>>>(
        q, protos, escratch, psum,
        (const float4*)logits, (const float4*)plabel, ptr_in,
        (float4*)out_classfy, labels, out_contl, out_qp, out_ptr,
        (const float4*)k, (const float4*)queue, queuep,
        (float4*)out_contf, (float4*)out_queue, out_qp);

    // 2) tail: normalize + proto EMA, interleaved roles
    tail_kernel<<<TAIL_GRID, 256, 0, s>>>(
        (const float4*)escratch, psum, q, protos, labels,
        (float4*)out_cluster, out_proto);
}